// round 14
// baseline (speedup 1.0000x reference)
#include <cuda_runtime.h>
#include <cstdint>
#include <math.h>

#define B_ 8
#define C_ 64
#define H_ 256
#define W_ 256
#define P_ (H_*W_)
#define K_ 2048
#define NFG 1024
#define NHARD 768
#define NRAND 256
#define NG 24              // B_ * 3 picks
#define NJT 16             // j-tiles per row (2048/128)
#define NTILES (NJT*(NJT+1)/2)   // 136 upper-triangle tile pairs
#define CAPMAX 8192
#define LOCCAP 1024
#define BCMAX 512
// exp((c-1)/T) = 2^(c*C1 + C0),  C1 = log2(e)/T
#define C1_ 20.609929155555663f
#define C0_ (-20.609929155555663f)

// -------- scratch (static __device__, no allocations) --------
__device__ uint32_t g_fgbm [B_*2048];           // 256 rows x 8 words per image
__device__ uint32_t g_dilbm[B_*2048];
__device__ int g_mpart[B_][8][3];               // pool-count partials (no atomics)
__device__ unsigned int g_hist[NG][2048];
__device__ int g_bstar[NG];
__device__ int g_r[NG];
__device__ unsigned long long g_cap[NG][CAPMAX]; // captured (value,idx) keys
__device__ unsigned long long g_cand[NG][BCMAX];
__device__ int g_ccnt[NG];
__device__ int g_ocnt[NG];
__device__ int g_bccnt[NG];
__device__ unsigned int g_hdone[NG];
__device__ unsigned int g_edone[NG];
__device__ unsigned int g_ldone[B_];
__device__ unsigned int g_rldone;
__device__ int   g_idx[B_*K_];
__device__ int   g_ys [B_*K_];
__device__ float g_fsn[B_*K_*C_];               // tf32-rounded normalized feats
__device__ float g_d [B_*K_*NJT];               // deterministic partials
__device__ float g_pp[B_*K_*NJT];
__device__ float g_loss_sum[B_];
__device__ int   g_valid[B_];

#define NZERO (NG*2048 + 5*NG + B_ + 1)

// -------- small PTX helpers --------
__device__ __forceinline__ float ex2f(float x) {
    float y; asm("ex2.approx.f32 %0, %1;" : "=f"(y) : "f"(x)); return y;
}
__device__ __forceinline__ float to_tf32(float x) {
    uint32_t y; asm("cvt.rna.tf32.f32 %0, %1;" : "=r"(y) : "f"(x));
    return __uint_as_float(y);
}
__device__ __forceinline__ void mma_tf32(float c[4], const float a[4], const float b[2]) {
    asm volatile(
        "mma.sync.aligned.m16n8k8.row.col.f32.tf32.tf32.f32 "
        "{%0,%1,%2,%3}, {%4,%5,%6,%7}, {%8,%9}, {%0,%1,%2,%3};"
        : "+f"(c[0]), "+f"(c[1]), "+f"(c[2]), "+f"(c[3])
        : "r"(__float_as_uint(a[0])), "r"(__float_as_uint(a[1])),
          "r"(__float_as_uint(a[2])), "r"(__float_as_uint(a[3])),
          "r"(__float_as_uint(b[0])), "r"(__float_as_uint(b[1])));
}

// -------- Threefry-2x32 (matches JAX threefry2x32 exactly) --------
__host__ __device__ inline void tf2x32(uint32_t k0, uint32_t k1,
                                       uint32_t x0, uint32_t x1,
                                       uint32_t& o0, uint32_t& o1) {
    uint32_t ks2 = k0 ^ k1 ^ 0x1BD11BDAu;
    x0 += k0; x1 += k1;
#define RR(r) { x0 += x1; x1 = (x1 << r) | (x1 >> (32 - r)); x1 ^= x0; }
    RR(13) RR(15) RR(26) RR(6)  x0 += k1;  x1 += ks2 + 1u;
    RR(17) RR(29) RR(16) RR(24) x0 += ks2; x1 += k0  + 2u;
    RR(13) RR(15) RR(26) RR(6)  x0 += k0;  x1 += k1  + 3u;
    RR(17) RR(29) RR(16) RR(24) x0 += k1;  x1 += ks2 + 4u;
    RR(13) RR(15) RR(26) RR(6)  x0 += ks2; x1 += k0  + 5u;
#undef RR
    o0 = x0; o1 = x1;
}

// mask bit test for pick from bitmap words
__device__ __forceinline__ bool inmask_bits(int pick, uint32_t fgw, uint32_t dlw, int bp) {
    int fg = (fgw >> bp) & 1, dl = (dlw >> bp) & 1;
    return (pick == 0) ? fg : (pick == 1) ? (dl && !fg) : !dl;   // fg => dl
}

// -------- ONE mask kernel: bit-packed 21x21 dilation + zeroing + counts -----
// grid (8 rowgroups, B_), 256 thr. Halo of 10 rows each side recomputed.
__global__ void __launch_bounds__(256) mask_kernel(const int* __restrict__ labels) {
    int b = blockIdx.y, rg = blockIdx.x;
    int t = threadIdx.x, w = t >> 5, l = t & 31;

    // piggyback: zero hist + counters (consumed only by later kernels)
    int gtid = (b * 8 + rg) * 256 + t;
    for (int z = gtid; z < NZERO; z += 64 * 256) {
        if (z < NG*2048) { ((unsigned int*)g_hist)[z] = 0u; continue; }
        int r = z - NG*2048;
        if      (r < NG)        g_ccnt[r] = 0;
        else if (r < 2*NG)      g_ocnt[r - NG] = 0;
        else if (r < 3*NG)      g_bccnt[r - 2*NG] = 0;
        else if (r < 4*NG)      g_hdone[r - 3*NG] = 0u;
        else if (r < 5*NG)      g_edone[r - 4*NG] = 0u;
        else if (r < 5*NG + B_) g_ldone[r - 5*NG] = 0u;
        else                    g_rldone = 0u;
    }

    __shared__ uint32_t sfg[52][8], srd[52][8];
    int r0 = rg * 32;
    for (int r = w; r < 52; r += 8) {                 // uniform per warp
        int gr = r0 - 10 + r;
        bool valid = (gr >= 0 && gr < H_);
        uint32_t wd[8];
        #pragma unroll
        for (int i = 0; i < 8; ++i) {
            int bit = 0;
            if (valid) bit = (labels[b * P_ + gr * W_ + i * 32 + l] == 1);
            wd[i] = __ballot_sync(0xFFFFFFFFu, bit);  // broadcast to all lanes
        }
        if (l < 8) {
            uint32_t prev = (l > 0) ? wd[l - 1] : 0u;
            uint32_t cur  = wd[l];
            uint32_t nxt  = (l < 7) ? wd[l + 1] : 0u;
            uint32_t res = cur;
            #pragma unroll
            for (int s = 1; s <= 10; ++s)
                res |= ((cur << s) | (prev >> (32 - s)))
                     | ((cur >> s) | (nxt  << (32 - s)));
            sfg[r][l] = cur;
            srd[r][l] = res;
        }
    }
    __syncthreads();
    // column dilation: thread -> (local row k, word wi)
    int k = t >> 3, wi = t & 7;
    uint32_t dil = 0;
    #pragma unroll
    for (int dr = 0; dr < 21; ++dr) dil |= srd[k + dr][wi];
    uint32_t fg = sfg[k + 10][wi];
    int grow = r0 + k;
    g_fgbm [b * 2048 + grow * 8 + wi] = fg;
    g_dilbm[b * 2048 + grow * 8 + wi] = dil;

    // pool-count partials: pick0=fg, pick1=dil&!fg, pick2=!dil
    int c0 = __popc(fg), c1 = __popc(dil & ~fg), c2 = __popc(~dil);
    #pragma unroll
    for (int o = 16; o; o >>= 1) {
        c0 += __shfl_xor_sync(0xFFFFFFFFu, c0, o);
        c1 += __shfl_xor_sync(0xFFFFFFFFu, c1, o);
        c2 += __shfl_xor_sync(0xFFFFFFFFu, c2, o);
    }
    __shared__ int pw[8][3];
    if (l == 0) { pw[w][0] = c0; pw[w][1] = c1; pw[w][2] = c2; }
    __syncthreads();
    if (t == 0) {
        int s0 = 0, s1 = 0, s2 = 0;
        #pragma unroll
        for (int q = 0; q < 8; ++q) { s0 += pw[q][0]; s1 += pw[q][1]; s2 += pw[q][2]; }
        g_mpart[b][rg][0] = s0; g_mpart[b][rg][1] = s1; g_mpart[b][rg][2] = s2;
    }
}

// -------- selection pass: MASK-FIRST hash + hist(subset) + CAPTURE ----------
struct KeyArg { uint32_t k[B_][3][2]; };

__global__ void __launch_bounds__(256) hash_hist_kernel(KeyArg ka) {
    int g = blockIdx.x, chunk = blockIdx.y;
    int b = g / 3, pick = g % 3;
    int n = (pick == 0) ? NFG : (pick == 1) ? NHARD : NRAND;
    uint32_t k0 = ka.k[b][pick][0], k1 = ka.k[b][pick][1];
    int t = threadIdx.x;
    int m = 0;
    #pragma unroll
    for (int q = 0; q < 8; ++q) m += g_mpart[b][q][pick];
    if (m < 1) m = 1;
    int span = (int)(((long long)6 * n * 2048 + m - 1) / m);   // ceil(6n*2048/m)
    if (span > 2048) span = 2048;
    int bfloor = 2048 - span;
    const uint32_t* fgb = g_fgbm  + b * 2048;
    const uint32_t* dlb = g_dilbm + b * 2048;

    __shared__ unsigned long long loc[LOCCAP];
    __shared__ int lcnt;
    if (t == 0) lcnt = 0;
    __syncthreads();

    for (int kk = 0; kk < 4; ++kk) {
        int p0 = chunk * 1024 + kk * 256 + t;
        // mask BEFORE hash: skip Threefry when neither pair half is masked
        int wi0 = p0 >> 5, bp = p0 & 31;
        bool m0 = inmask_bits(pick, fgb[wi0],        dlb[wi0],        bp);
        bool m1 = inmask_bits(pick, fgb[wi0 + 1024], dlb[wi0 + 1024], bp);
        if (!m0 && !m1) continue;
        uint32_t o0, o1;
        tf2x32(k0, k1, (uint32_t)p0, (uint32_t)(p0 + 32768), o0, o1);
        #pragma unroll
        for (int hh = 0; hh < 2; ++hh) {
            bool mm = hh ? m1 : m0;
            if (!mm) continue;
            int p = p0 + hh * 32768;
            uint32_t u = hh ? o1 : o0;
            int bin = (int)(u >> 21);
            if (bin < bfloor) continue;
            atomicAdd(&g_hist[g][bin], 1u);
            // value desc, then index asc (top_k tie rule)
            unsigned long long key = ((unsigned long long)(u >> 9) << 16)
                                   | (unsigned long long)(0xFFFFu - (uint32_t)p);
            int pos = atomicAdd(&lcnt, 1);            // SMEM atomic
            if (pos < LOCCAP) loc[pos] = key;
            else {                                     // unexpected overflow
                int gp = atomicAdd(&g_ccnt[g], 1);
                if (gp < CAPMAX) g_cap[g][gp] = key;
            }
        }
    }
    __syncthreads();
    int c = lcnt < LOCCAP ? lcnt : LOCCAP;
    __shared__ int sbase;
    if (t == 0) sbase = atomicAdd(&g_ccnt[g], c);          // ONE reservation/block
    __syncthreads();
    for (int ci = t; ci < c; ci += 256) {
        int gp = sbase + ci;
        if (gp < CAPMAX) g_cap[g][gp] = loc[ci];
    }
    __syncthreads();
    __shared__ int lastFlag;
    if (t == 0) {
        __threadfence();
        lastFlag = (atomicAdd(&g_hdone[g], 1u) == 31u);
    }
    __syncthreads();
    if (!lastFlag) return;

    // ---- fused scan: parallel prefix over 256 8-bin segments (descending) --
    unsigned int hv[8], s8 = 0;
    #pragma unroll
    for (int k = 0; k < 8; ++k) { hv[k] = g_hist[g][2047 - (t * 8 + k)]; s8 += hv[k]; }
    __shared__ unsigned int part[256];
    part[t] = s8;
    __syncthreads();
    #pragma unroll
    for (int off = 1; off < 256; off <<= 1) {
        unsigned int v = (t >= off) ? part[t - off] : 0u;
        __syncthreads();
        part[t] += v;
        __syncthreads();
    }
    int incl = (int)part[t];
    int before = incl - (int)s8;
    if (before < n && incl >= n) {          // exactly one owner thread
        int cum = before, bstar = 0, above = before;
        #pragma unroll
        for (int k = 0; k < 8; ++k) {
            int q = 2047 - (t * 8 + k);
            int hh = (int)hv[k];
            if (cum + hh >= n) { bstar = q; above = cum; break; }
            cum += hh;
        }
        g_bstar[g] = bstar;
        g_r[g] = n - above;
    }
}

// -------- tiny emit from compact list (grid NG x 4, 256 thr) --------
// warp-aggregated slot reservation; last block does boundary rank select.
__global__ void __launch_bounds__(256) emit_kernel() {
    int g = blockIdx.x, quarter = blockIdx.y;
    int b = g / 3, pick = g % 3;
    int base = b * K_ + ((pick == 0) ? 0 : (pick == 1) ? NFG : (NFG + NHARD));
    int bstar = g_bstar[g];
    int t = threadIdx.x, lane = t & 31;
    int cnt = g_ccnt[g]; if (cnt > CAPMAX) cnt = CAPMAX;

    #pragma unroll
    for (int it = 0; it < 8; ++it) {                  // fixed trip count: warp-uniform
        int ci = quarter * 2048 + it * 256 + t;
        bool valid = (ci < cnt);
        unsigned long long v = valid ? g_cap[g][ci] : 0ull;
        int bin = (int)(v >> 28);
        bool win = valid && (bin > bstar);
        unsigned int mk = __ballot_sync(0xFFFFFFFFu, win);
        if (mk) {
            int ldr = __ffs(mk) - 1;
            int sb_ = 0;
            if (lane == ldr) sb_ = atomicAdd(&g_ocnt[g], __popc(mk));
            sb_ = __shfl_sync(0xFFFFFFFFu, sb_, ldr);
            if (win)
                g_idx[base + sb_ + __popc(mk & ((1u << lane) - 1u))]
                    = 0xFFFF - (int)(v & 0xFFFFull);
        }
        bool bnd = valid && (bin == bstar);           // ~16 total: plain atomics fine
        if (bnd) {
            int c2 = atomicAdd(&g_bccnt[g], 1);
            if (c2 < BCMAX) g_cand[g][c2] = v;
        }
    }
    __syncthreads();
    __shared__ int lastFlag;
    if (t == 0) {
        __threadfence();
        lastFlag = (atomicAdd(&g_edone[g], 1u) == 3u);
    }
    __syncthreads();
    if (!lastFlag) return;

    // ---- boundary-bin rank select ----
    int c = g_bccnt[g]; if (c > BCMAX) c = BCMAX;
    int r = g_r[g];
    __shared__ unsigned long long cd[BCMAX];
    for (int ci = t; ci < c; ci += 256) cd[ci] = g_cand[g][ci];
    __syncthreads();
    for (int ci = t; ci < c; ci += 256) {
        unsigned long long v = cd[ci];
        int rank = 0;
        for (int q = 0; q < c; ++q) rank += (cd[q] > v);
        if (rank < r) {
            int slot = atomicAdd(&g_ocnt[g], 1);
            g_idx[base + slot] = 0xFFFF - (int)(v & 0xFFFFull);
        }
    }
}

// -------- gather + L2-normalize + tf32 round (one warp per sample) --------
__global__ void gather_kernel(const float* __restrict__ feats) {
    int gw   = (blockIdx.x * blockDim.x + threadIdx.x) >> 5;
    int lane = threadIdx.x & 31;
    if (gw >= B_ * K_) return;
    int b = gw / K_;
    int p = g_idx[gw];
    const float* f = feats + (size_t)b * C_ * P_ + p;
    float v0 = f[(size_t)lane * P_];
    float v1 = f[(size_t)(lane + 32) * P_];
    float ss = v0 * v0 + v1 * v1;
    #pragma unroll
    for (int o = 16; o; o >>= 1) ss += __shfl_xor_sync(0xFFFFFFFFu, ss, o);
    float inv = 1.0f / fmaxf(sqrtf(ss), 1e-12f);
    float* out = g_fsn + (size_t)gw * C_;
    out[lane]      = to_tf32(v0 * inv);   // tf32-matmul input semantics
    out[lane + 32] = to_tf32(v1 * inv);
    if (lane == 0)                        // labels are {0,1}: ys == fg bit
        g_ys[gw] = (int)((g_fgbm[b * 2048 + (p >> 5)] >> (p & 31)) & 1u);
}

// -------- fused Gram (tf32 mma, symmetric) + per-image rowloss tail ---------
// grid (136, b=8), 256 thr = 8 warps (4 i-warps x 2 j-warps)
__global__ void __launch_bounds__(256, 2) loss_mma_kernel(float* out) {
    extern __shared__ float smem[];
    float* xi = smem;            // 128 x 64
    float* xj = smem + 8192;     // 128 x 64
    __shared__ signed char ysi[128], ysj[128];
    __shared__ float rowd[128][2], rowp[128][2];
    __shared__ float cold[128][4], colp[128][4];

    int b = blockIdx.y;
    int u = blockIdx.x;
    int it = 0;
    while (u >= NJT - it) { u -= NJT - it; ++it; }
    int jt = it + u;
    bool diagT = (it == jt);
    int t = threadIdx.x;

    const float4* src_i = (const float4*)(g_fsn + ((size_t)b * K_ + it * 128) * C_);
    const float4* src_j = (const float4*)(g_fsn + ((size_t)b * K_ + jt * 128) * C_);
    for (int q = t; q < 2048; q += 256) {
        int row = q >> 4, c4 = q & 15;
        int dst = (row << 6) + ((c4 ^ (row & 7)) << 2);
        *(float4*)(xi + dst) = src_i[q];
        *(float4*)(xj + dst) = src_j[q];
    }
    if (t < 128) ysi[t] = (signed char)g_ys[b * K_ + it * 128 + t];
    else         ysj[t - 128] = (signed char)g_ys[b * K_ + jt * 128 + (t - 128)];
    __syncthreads();

    int w    = t >> 5;
    int lane = t & 31;
    int wi = w >> 1;             // 0..3 : i-strip of 32 rows
    int wj = w & 1;              // 0..1 : j-strip of 64 cols
    int g   = lane >> 2;         // groupID
    int tig = lane & 3;          // thread-in-group

    float c[2][8][4];
    #pragma unroll
    for (int m = 0; m < 2; ++m)
        #pragma unroll
        for (int n = 0; n < 8; ++n)
            { c[m][n][0]=0.f; c[m][n][1]=0.f; c[m][n][2]=0.f; c[m][n][3]=0.f; }

    #pragma unroll
    for (int ks = 0; ks < 8; ++ks) {
        int c4a = 2 * ks, c4b = 2 * ks + 1;
        float a[2][4];
        #pragma unroll
        for (int m = 0; m < 2; ++m) {
            int r0 = wi * 32 + m * 16 + g;
            int r1 = r0 + 8;
            int x0 = (r0 & 7);
            a[m][0] = xi[(r0 << 6) + ((c4a ^ x0) << 2) + tig];
            a[m][2] = xi[(r0 << 6) + ((c4b ^ x0) << 2) + tig];
            a[m][1] = xi[(r1 << 6) + ((c4a ^ x0) << 2) + tig];
            a[m][3] = xi[(r1 << 6) + ((c4b ^ x0) << 2) + tig];
        }
        float bf[8][2];
        #pragma unroll
        for (int n = 0; n < 8; ++n) {
            int jr = wj * 64 + n * 8 + g;
            int xo = (jr & 7);
            bf[n][0] = xj[(jr << 6) + ((c4a ^ xo) << 2) + tig];
            bf[n][1] = xj[(jr << 6) + ((c4b ^ xo) << 2) + tig];
        }
        #pragma unroll
        for (int m = 0; m < 2; ++m)
            #pragma unroll
            for (int n = 0; n < 8; ++n)
                mma_tf32(c[m][n], a[m], bf[n]);
    }

    // epilogue: exp + masked row sums + (off-diag) col sums, fixed order
    signed char yj[16];
    #pragma unroll
    for (int n = 0; n < 8; ++n) {
        int col = wj * 64 + n * 8 + tig * 2;
        yj[2*n]   = ysj[col];
        yj[2*n+1] = ysj[col + 1];
    }
    float cd0[8], cd1[8], cp0[8], cp1[8];
    #pragma unroll
    for (int n = 0; n < 8; ++n) { cd0[n]=0.f; cd1[n]=0.f; cp0[n]=0.f; cp1[n]=0.f; }

    #pragma unroll
    for (int m = 0; m < 2; ++m) {
        int r0 = wi * 32 + m * 16 + g;
        int r1 = r0 + 8;
        int y0 = ysi[r0], y1 = ysi[r1];
        float d0 = 0.f, p0 = 0.f, d1 = 0.f, p1 = 0.f;
        #pragma unroll
        for (int n = 0; n < 8; ++n) {
            int col = wj * 64 + n * 8 + tig * 2;
            float e00 = ex2f(fmaf(c[m][n][0], C1_, C0_));
            float e01 = ex2f(fmaf(c[m][n][1], C1_, C0_));
            float e10 = ex2f(fmaf(c[m][n][2], C1_, C0_));
            float e11 = ex2f(fmaf(c[m][n][3], C1_, C0_));
            if (diagT) {
                if (r0 == col)     e00 = 0.f;
                if (r0 == col + 1) e01 = 0.f;
                if (r1 == col)     e10 = 0.f;
                if (r1 == col + 1) e11 = 0.f;
            }
            bool q00 = (y0 == yj[2*n]), q01 = (y0 == yj[2*n+1]);
            bool q10 = (y1 == yj[2*n]), q11 = (y1 == yj[2*n+1]);
            d0 += e00 + e01;
            d1 += e10 + e11;
            p0 += (q00 ? e00 : 0.f) + (q01 ? e01 : 0.f);
            p1 += (q10 ? e10 : 0.f) + (q11 ? e11 : 0.f);
            if (!diagT) {
                cd0[n] += e00 + e10;
                cd1[n] += e01 + e11;
                cp0[n] += (q00 ? e00 : 0.f) + (q10 ? e10 : 0.f);
                cp1[n] += (q01 ? e01 : 0.f) + (q11 ? e11 : 0.f);
            }
        }
        #pragma unroll
        for (int o = 1; o <= 2; o <<= 1) {
            d0 += __shfl_xor_sync(0xFFFFFFFFu, d0, o);
            p0 += __shfl_xor_sync(0xFFFFFFFFu, p0, o);
            d1 += __shfl_xor_sync(0xFFFFFFFFu, d1, o);
            p1 += __shfl_xor_sync(0xFFFFFFFFu, p1, o);
        }
        if (tig == 0) {
            rowd[r0][wj] = d0; rowp[r0][wj] = p0;
            rowd[r1][wj] = d1; rowp[r1][wj] = p1;
        }
    }

    if (!diagT) {
        #pragma unroll
        for (int n = 0; n < 8; ++n) {
            #pragma unroll
            for (int o = 4; o <= 16; o <<= 1) {
                cd0[n] += __shfl_xor_sync(0xFFFFFFFFu, cd0[n], o);
                cd1[n] += __shfl_xor_sync(0xFFFFFFFFu, cd1[n], o);
                cp0[n] += __shfl_xor_sync(0xFFFFFFFFu, cp0[n], o);
                cp1[n] += __shfl_xor_sync(0xFFFFFFFFu, cp1[n], o);
            }
        }
        if (lane < 4) {          // g == 0, tig == lane
            #pragma unroll
            for (int n = 0; n < 8; ++n) {
                int col = wj * 64 + n * 8 + lane * 2;
                cold[col][wi]     = cd0[n]; colp[col][wi]     = cp0[n];
                cold[col + 1][wi] = cd1[n]; colp[col + 1][wi] = cp1[n];
            }
        }
    }
    __syncthreads();
    if (t < 128) {
        int gi = b * K_ + it * 128 + t;
        g_d [gi * NJT + jt] = rowd[t][0] + rowd[t][1];
        g_pp[gi * NJT + jt] = rowp[t][0] + rowp[t][1];
        if (!diagT) {
            int gj = b * K_ + jt * 128 + t;
            g_d [gj * NJT + it] = ((cold[t][0] + cold[t][1]) + (cold[t][2] + cold[t][3]));
            g_pp[gj * NJT + it] = ((colp[t][0] + colp[t][1]) + (colp[t][2] + colp[t][3]));
        }
    }

    // ---- per-image rowloss tail: last tile-block of image b ----
    __syncthreads();
    __shared__ int lastFlag;
    if (t == 0) {
        __threadfence();
        lastFlag = (atomicAdd(&g_ldone[b], 1u) == (unsigned)(NTILES - 1));
    }
    __syncthreads();
    if (!lastFlag) return;

    float ls = 0.0f; int cnt2 = 0;
    for (int i = t; i < K_; i += 256) {
        int yi = g_ys[b * K_ + i];
        float dv = 0.0f, pv = 0.0f;
        #pragma unroll
        for (int js = 0; js < NJT; ++js) {
            dv += g_d [(b * K_ + i) * NJT + js];
            pv += g_pp[(b * K_ + i) * NJT + js];
        }
        if (yi == 1 && pv > 0.0f) {
            ls += logf(fmaxf(dv, 1e-8f)) - logf(fmaxf(pv, 1e-8f));
            cnt2++;
        }
    }
    __shared__ float ss2[256];
    __shared__ int   sc2[256];
    ss2[t] = ls; sc2[t] = cnt2;
    __syncthreads();
    for (int o = 128; o; o >>= 1) {
        if (t < o) { ss2[t] += ss2[t + o]; sc2[t] += sc2[t + o]; }
        __syncthreads();
    }
    if (t == 0) {
        g_loss_sum[b] = ss2[0];
        g_valid[b]    = sc2[0];
        __threadfence();
        if (atomicAdd(&g_rldone, 1u) == (unsigned)(B_ - 1)) {
            float s = 0.0f;
            for (int bb = 0; bb < B_; ++bb) {    // fixed order -> deterministic
                int v = g_valid[bb]; if (v < 1) v = 1;
                s += g_loss_sum[bb] / (float)v;
            }
            out[0] = s / (float)B_;
        }
    }
}

// -------- launch --------
extern "C" void kernel_launch(void* const* d_in, const int* in_sizes, int n_in,
                              void* d_out, int out_size) {
    const float* feats  = (const float*)d_in[0];
    const int*   labels = (const int*)d_in[1];

    // Derive JAX keys host-side (deterministic; baked into graph as kernel args).
    KeyArg ka;
    uint32_t out16[16];
    for (int j = 0; j < 8; ++j)
        tf2x32(0u, 1u, (uint32_t)j, (uint32_t)(8 + j), out16[j], out16[8 + j]);
    for (int b = 0; b < B_; ++b) {
        uint32_t kb0 = out16[2 * b], kb1 = out16[2 * b + 1];
        uint32_t o6[6];
        for (int j = 0; j < 3; ++j)
            tf2x32(kb0, kb1, (uint32_t)j, (uint32_t)(3 + j), o6[j], o6[3 + j]);
        ka.k[b][0][0] = o6[0]; ka.k[b][0][1] = o6[1];   // k1 -> fg pick
        ka.k[b][1][0] = o6[2]; ka.k[b][1][1] = o6[3];   // k2 -> ring pick
        ka.k[b][2][0] = o6[4]; ka.k[b][2][1] = o6[5];   // k3 -> bg pick
    }

    // 64 KB dynamic smem opt-in (idempotent; one-shot; graph-safe)
    static_assert(2 * 128 * 64 * sizeof(float) == 65536, "smem size");
    static bool s_attr_done = false;
    if (!s_attr_done) {
        cudaFuncSetAttribute(loss_mma_kernel,
                             cudaFuncAttributeMaxDynamicSharedMemorySize, 65536);
        s_attr_done = true;
    }

    mask_kernel<<<dim3(8, B_), 256>>>(labels);
    hash_hist_kernel<<<dim3(NG, 32), 256>>>(ka);
    emit_kernel<<<dim3(NG, 4), 256>>>();
    gather_kernel<<<(B_ * K_ * 32 + 255) / 256, 256>>>(feats);
    loss_mma_kernel<<<dim3(NTILES, B_), 256, 65536>>>((float*)d_out);
}

// round 15
// speedup vs baseline: 1.0488x; 1.0488x over previous
#include <cuda_runtime.h>
#include <cstdint>
#include <math.h>

#define B_ 8
#define C_ 64
#define H_ 256
#define W_ 256
#define P_ (H_*W_)
#define K_ 2048
#define NFG 1024
#define NHARD 768
#define NRAND 256
#define NG 24              // B_ * 3 picks
#define NJT 16             // j-tiles per row (2048/128)
#define NTILES (NJT*(NJT+1)/2)   // 136 upper-triangle tile pairs
#define CAPMAX 8192
#define LOCCAP 1024
#define BCMAX 512
// exp((c-1)/T) = 2^(c*C1 + C0),  C1 = log2(e)/T
#define C1_ 20.609929155555663f
#define C0_ (-20.609929155555663f)

// -------- scratch (static __device__, no allocations) --------
__device__ uint32_t g_fgbm [B_*2048];           // 256 rows x 8 words per image
__device__ uint32_t g_dilbm[B_*2048];
__device__ int g_mpart[B_][8][3];               // pool-count partials (no atomics)
__device__ unsigned int g_hist[NG][2048];
__device__ int g_bstar[NG];
__device__ int g_r[NG];
__device__ unsigned long long g_cap[NG][CAPMAX]; // captured (value,idx) keys
__device__ unsigned long long g_cand[NG][BCMAX];
__device__ int g_ccnt[NG];
__device__ int g_ocnt[NG];
__device__ int g_bccnt[NG];
__device__ unsigned int g_hdone[NG];
__device__ unsigned int g_edone[NG];
__device__ unsigned int g_rldone;
__device__ int   g_idx[B_*K_];
__device__ int   g_ys [B_*K_];
__device__ float g_fsn[B_*K_*C_];               // tf32-rounded normalized feats
__device__ float g_d [B_*K_*NJT];               // deterministic partials
__device__ float g_pp[B_*K_*NJT];
__device__ float g_loss_sum[B_];
__device__ int   g_valid[B_];

#define NZERO (NG*2048 + 5*NG + 1)

// -------- small PTX helpers --------
__device__ __forceinline__ float ex2f(float x) {
    float y; asm("ex2.approx.f32 %0, %1;" : "=f"(y) : "f"(x)); return y;
}
__device__ __forceinline__ float to_tf32(float x) {
    uint32_t y; asm("cvt.rna.tf32.f32 %0, %1;" : "=r"(y) : "f"(x));
    return __uint_as_float(y);
}
__device__ __forceinline__ void mma_tf32(float c[4], const float a[4], const float b[2]) {
    asm volatile(
        "mma.sync.aligned.m16n8k8.row.col.f32.tf32.tf32.f32 "
        "{%0,%1,%2,%3}, {%4,%5,%6,%7}, {%8,%9}, {%0,%1,%2,%3};"
        : "+f"(c[0]), "+f"(c[1]), "+f"(c[2]), "+f"(c[3])
        : "r"(__float_as_uint(a[0])), "r"(__float_as_uint(a[1])),
          "r"(__float_as_uint(a[2])), "r"(__float_as_uint(a[3])),
          "r"(__float_as_uint(b[0])), "r"(__float_as_uint(b[1])));
}

// -------- Threefry-2x32 (matches JAX threefry2x32 exactly) --------
__host__ __device__ inline void tf2x32(uint32_t k0, uint32_t k1,
                                       uint32_t x0, uint32_t x1,
                                       uint32_t& o0, uint32_t& o1) {
    uint32_t ks2 = k0 ^ k1 ^ 0x1BD11BDAu;
    x0 += k0; x1 += k1;
#define RR(r) { x0 += x1; x1 = (x1 << r) | (x1 >> (32 - r)); x1 ^= x0; }
    RR(13) RR(15) RR(26) RR(6)  x0 += k1;  x1 += ks2 + 1u;
    RR(17) RR(29) RR(16) RR(24) x0 += ks2; x1 += k0  + 2u;
    RR(13) RR(15) RR(26) RR(6)  x0 += k0;  x1 += k1  + 3u;
    RR(17) RR(29) RR(16) RR(24) x0 += k1;  x1 += ks2 + 4u;
    RR(13) RR(15) RR(26) RR(6)  x0 += ks2; x1 += k0  + 5u;
#undef RR
    o0 = x0; o1 = x1;
}

// mask bit test for pick from bitmap words
__device__ __forceinline__ bool inmask_bits(int pick, uint32_t fgw, uint32_t dlw, int bp) {
    int fg = (fgw >> bp) & 1, dl = (dlw >> bp) & 1;
    return (pick == 0) ? fg : (pick == 1) ? (dl && !fg) : !dl;   // fg => dl
}

// -------- ONE mask kernel: bit-packed 21x21 dilation + zeroing + counts -----
// grid (8 rowgroups, B_), 256 thr. Halo of 10 rows each side recomputed.
__global__ void __launch_bounds__(256) mask_kernel(const int* __restrict__ labels) {
    int b = blockIdx.y, rg = blockIdx.x;
    int t = threadIdx.x, w = t >> 5, l = t & 31;

    // piggyback: zero hist + counters (consumed only by later kernels)
    int gtid = (b * 8 + rg) * 256 + t;
    for (int z = gtid; z < NZERO; z += 64 * 256) {
        if (z < NG*2048) { ((unsigned int*)g_hist)[z] = 0u; continue; }
        int r = z - NG*2048;
        if      (r < NG)    g_ccnt[r] = 0;
        else if (r < 2*NG)  g_ocnt[r - NG] = 0;
        else if (r < 3*NG)  g_bccnt[r - 2*NG] = 0;
        else if (r < 4*NG)  g_hdone[r - 3*NG] = 0u;
        else if (r < 5*NG)  g_edone[r - 4*NG] = 0u;
        else                g_rldone = 0u;
    }

    __shared__ uint32_t sfg[52][8], srd[52][8];
    int r0 = rg * 32;
    for (int r = w; r < 52; r += 8) {                 // uniform per warp
        int gr = r0 - 10 + r;
        bool valid = (gr >= 0 && gr < H_);
        uint32_t wd[8];
        #pragma unroll
        for (int i = 0; i < 8; ++i) {
            int bit = 0;
            if (valid) bit = (labels[b * P_ + gr * W_ + i * 32 + l] == 1);
            wd[i] = __ballot_sync(0xFFFFFFFFu, bit);  // broadcast to all lanes
        }
        if (l < 8) {
            uint32_t prev = (l > 0) ? wd[l - 1] : 0u;
            uint32_t cur  = wd[l];
            uint32_t nxt  = (l < 7) ? wd[l + 1] : 0u;
            uint32_t res = cur;
            #pragma unroll
            for (int s = 1; s <= 10; ++s)
                res |= ((cur << s) | (prev >> (32 - s)))
                     | ((cur >> s) | (nxt  << (32 - s)));
            sfg[r][l] = cur;
            srd[r][l] = res;
        }
    }
    __syncthreads();
    // column dilation: thread -> (local row k, word wi)
    int k = t >> 3, wi = t & 7;
    uint32_t dil = 0;
    #pragma unroll
    for (int dr = 0; dr < 21; ++dr) dil |= srd[k + dr][wi];
    uint32_t fg = sfg[k + 10][wi];
    int grow = r0 + k;
    g_fgbm [b * 2048 + grow * 8 + wi] = fg;
    g_dilbm[b * 2048 + grow * 8 + wi] = dil;

    // pool-count partials: pick0=fg, pick1=dil&!fg, pick2=!dil
    int c0 = __popc(fg), c1 = __popc(dil & ~fg), c2 = __popc(~dil);
    #pragma unroll
    for (int o = 16; o; o >>= 1) {
        c0 += __shfl_xor_sync(0xFFFFFFFFu, c0, o);
        c1 += __shfl_xor_sync(0xFFFFFFFFu, c1, o);
        c2 += __shfl_xor_sync(0xFFFFFFFFu, c2, o);
    }
    __shared__ int pw[8][3];
    if (l == 0) { pw[w][0] = c0; pw[w][1] = c1; pw[w][2] = c2; }
    __syncthreads();
    if (t == 0) {
        int s0 = 0, s1 = 0, s2 = 0;
        #pragma unroll
        for (int q = 0; q < 8; ++q) { s0 += pw[q][0]; s1 += pw[q][1]; s2 += pw[q][2]; }
        g_mpart[b][rg][0] = s0; g_mpart[b][rg][1] = s1; g_mpart[b][rg][2] = s2;
    }
}

// -------- selection pass: MASK-FIRST hash + hist(subset) + CAPTURE ----------
struct KeyArg { uint32_t k[B_][3][2]; };

__global__ void __launch_bounds__(256) hash_hist_kernel(KeyArg ka) {
    int g = blockIdx.x, chunk = blockIdx.y;
    int b = g / 3, pick = g % 3;
    int n = (pick == 0) ? NFG : (pick == 1) ? NHARD : NRAND;
    uint32_t k0 = ka.k[b][pick][0], k1 = ka.k[b][pick][1];
    int t = threadIdx.x;
    int m = 0;
    #pragma unroll
    for (int q = 0; q < 8; ++q) m += g_mpart[b][q][pick];
    if (m < 1) m = 1;
    int span = (int)(((long long)6 * n * 2048 + m - 1) / m);   // ceil(6n*2048/m)
    if (span > 2048) span = 2048;
    int bfloor = 2048 - span;
    const uint32_t* fgb = g_fgbm  + b * 2048;
    const uint32_t* dlb = g_dilbm + b * 2048;

    __shared__ unsigned long long loc[LOCCAP];
    __shared__ int lcnt;
    if (t == 0) lcnt = 0;
    __syncthreads();

    for (int kk = 0; kk < 4; ++kk) {
        int p0 = chunk * 1024 + kk * 256 + t;
        // mask BEFORE hash: skip Threefry when neither pair half is masked
        int wi0 = p0 >> 5, bp = p0 & 31;
        bool m0 = inmask_bits(pick, fgb[wi0],        dlb[wi0],        bp);
        bool m1 = inmask_bits(pick, fgb[wi0 + 1024], dlb[wi0 + 1024], bp);
        if (!m0 && !m1) continue;
        uint32_t o0, o1;
        tf2x32(k0, k1, (uint32_t)p0, (uint32_t)(p0 + 32768), o0, o1);
        #pragma unroll
        for (int hh = 0; hh < 2; ++hh) {
            bool mm = hh ? m1 : m0;
            if (!mm) continue;
            int p = p0 + hh * 32768;
            uint32_t u = hh ? o1 : o0;
            int bin = (int)(u >> 21);
            if (bin < bfloor) continue;
            atomicAdd(&g_hist[g][bin], 1u);
            // value desc, then index asc (top_k tie rule)
            unsigned long long key = ((unsigned long long)(u >> 9) << 16)
                                   | (unsigned long long)(0xFFFFu - (uint32_t)p);
            int pos = atomicAdd(&lcnt, 1);            // SMEM atomic
            if (pos < LOCCAP) loc[pos] = key;
            else {                                     // unexpected overflow
                int gp = atomicAdd(&g_ccnt[g], 1);
                if (gp < CAPMAX) g_cap[g][gp] = key;
            }
        }
    }
    __syncthreads();
    int c = lcnt < LOCCAP ? lcnt : LOCCAP;
    __shared__ int sbase;
    if (t == 0) sbase = atomicAdd(&g_ccnt[g], c);          // ONE reservation/block
    __syncthreads();
    for (int ci = t; ci < c; ci += 256) {
        int gp = sbase + ci;
        if (gp < CAPMAX) g_cap[g][gp] = loc[ci];
    }
    __syncthreads();
    __shared__ int lastFlag;
    if (t == 0) {
        __threadfence();
        lastFlag = (atomicAdd(&g_hdone[g], 1u) == 31u);
    }
    __syncthreads();
    if (!lastFlag) return;

    // ---- fused scan: parallel prefix over 256 8-bin segments (descending) --
    unsigned int hv[8], s8 = 0;
    #pragma unroll
    for (int k = 0; k < 8; ++k) { hv[k] = g_hist[g][2047 - (t * 8 + k)]; s8 += hv[k]; }
    __shared__ unsigned int part[256];
    part[t] = s8;
    __syncthreads();
    #pragma unroll
    for (int off = 1; off < 256; off <<= 1) {
        unsigned int v = (t >= off) ? part[t - off] : 0u;
        __syncthreads();
        part[t] += v;
        __syncthreads();
    }
    int incl = (int)part[t];
    int before = incl - (int)s8;
    if (before < n && incl >= n) {          // exactly one owner thread
        int cum = before, bstar = 0, above = before;
        #pragma unroll
        for (int k = 0; k < 8; ++k) {
            int q = 2047 - (t * 8 + k);
            int hh = (int)hv[k];
            if (cum + hh >= n) { bstar = q; above = cum; break; }
            cum += hh;
        }
        g_bstar[g] = bstar;
        g_r[g] = n - above;
    }
}

// -------- tiny emit from compact list (grid NG x 4, 256 thr) --------
// warp-aggregated slot reservation; last block does boundary rank select.
__global__ void __launch_bounds__(256) emit_kernel() {
    int g = blockIdx.x, quarter = blockIdx.y;
    int b = g / 3, pick = g % 3;
    int base = b * K_ + ((pick == 0) ? 0 : (pick == 1) ? NFG : (NFG + NHARD));
    int bstar = g_bstar[g];
    int t = threadIdx.x, lane = t & 31;
    int cnt = g_ccnt[g]; if (cnt > CAPMAX) cnt = CAPMAX;

    #pragma unroll
    for (int it = 0; it < 8; ++it) {                  // fixed trip count: warp-uniform
        int ci = quarter * 2048 + it * 256 + t;
        bool valid = (ci < cnt);
        unsigned long long v = valid ? g_cap[g][ci] : 0ull;
        int bin = (int)(v >> 28);
        bool win = valid && (bin > bstar);
        unsigned int mk = __ballot_sync(0xFFFFFFFFu, win);
        if (mk) {
            int ldr = __ffs(mk) - 1;
            int sb_ = 0;
            if (lane == ldr) sb_ = atomicAdd(&g_ocnt[g], __popc(mk));
            sb_ = __shfl_sync(0xFFFFFFFFu, sb_, ldr);
            if (win)
                g_idx[base + sb_ + __popc(mk & ((1u << lane) - 1u))]
                    = 0xFFFF - (int)(v & 0xFFFFull);
        }
        bool bnd = valid && (bin == bstar);           // ~16 total: plain atomics fine
        if (bnd) {
            int c2 = atomicAdd(&g_bccnt[g], 1);
            if (c2 < BCMAX) g_cand[g][c2] = v;
        }
    }
    __syncthreads();
    __shared__ int lastFlag;
    if (t == 0) {
        __threadfence();
        lastFlag = (atomicAdd(&g_edone[g], 1u) == 3u);
    }
    __syncthreads();
    if (!lastFlag) return;

    // ---- boundary-bin rank select ----
    int c = g_bccnt[g]; if (c > BCMAX) c = BCMAX;
    int r = g_r[g];
    __shared__ unsigned long long cd[BCMAX];
    for (int ci = t; ci < c; ci += 256) cd[ci] = g_cand[g][ci];
    __syncthreads();
    for (int ci = t; ci < c; ci += 256) {
        unsigned long long v = cd[ci];
        int rank = 0;
        for (int q = 0; q < c; ++q) rank += (cd[q] > v);
        if (rank < r) {
            int slot = atomicAdd(&g_ocnt[g], 1);
            g_idx[base + slot] = 0xFFFF - (int)(v & 0xFFFFull);
        }
    }
}

// -------- gather + L2-normalize + tf32 round (one warp per sample) --------
__global__ void gather_kernel(const float* __restrict__ feats) {
    int gw   = (blockIdx.x * blockDim.x + threadIdx.x) >> 5;
    int lane = threadIdx.x & 31;
    if (gw >= B_ * K_) return;
    int b = gw / K_;
    int p = g_idx[gw];
    const float* f = feats + (size_t)b * C_ * P_ + p;
    float v0 = f[(size_t)lane * P_];
    float v1 = f[(size_t)(lane + 32) * P_];
    float ss = v0 * v0 + v1 * v1;
    #pragma unroll
    for (int o = 16; o; o >>= 1) ss += __shfl_xor_sync(0xFFFFFFFFu, ss, o);
    float inv = 1.0f / fmaxf(sqrtf(ss), 1e-12f);
    float* out = g_fsn + (size_t)gw * C_;
    out[lane]      = to_tf32(v0 * inv);   // tf32-matmul input semantics
    out[lane + 32] = to_tf32(v1 * inv);
    if (lane == 0)                        // labels are {0,1}: ys == fg bit
        g_ys[gw] = (int)((g_fgbm[b * 2048 + (p >> 5)] >> (p & 31)) & 1u);
}

// -------- fused Gram (tf32 mma, SYMMETRIC: upper-triangle tiles only) -------
// grid (136, b=8), 256 thr = 8 warps (4 i-warps x 2 j-warps)
__global__ void __launch_bounds__(256, 2) loss_mma_kernel() {
    extern __shared__ float smem[];
    float* xi = smem;            // 128 x 64
    float* xj = smem + 8192;     // 128 x 64
    __shared__ signed char ysi[128], ysj[128];
    __shared__ float rowd[128][2], rowp[128][2];
    __shared__ float cold[128][4], colp[128][4];

    int b = blockIdx.y;
    int u = blockIdx.x;
    int it = 0;
    while (u >= NJT - it) { u -= NJT - it; ++it; }
    int jt = it + u;
    bool diagT = (it == jt);
    int t = threadIdx.x;

    const float4* src_i = (const float4*)(g_fsn + ((size_t)b * K_ + it * 128) * C_);
    const float4* src_j = (const float4*)(g_fsn + ((size_t)b * K_ + jt * 128) * C_);
    for (int q = t; q < 2048; q += 256) {
        int row = q >> 4, c4 = q & 15;
        int dst = (row << 6) + ((c4 ^ (row & 7)) << 2);
        *(float4*)(xi + dst) = src_i[q];
        *(float4*)(xj + dst) = src_j[q];
    }
    if (t < 128) ysi[t] = (signed char)g_ys[b * K_ + it * 128 + t];
    else         ysj[t - 128] = (signed char)g_ys[b * K_ + jt * 128 + (t - 128)];
    __syncthreads();

    int w    = t >> 5;
    int lane = t & 31;
    int wi = w >> 1;             // 0..3 : i-strip of 32 rows
    int wj = w & 1;              // 0..1 : j-strip of 64 cols
    int g   = lane >> 2;         // groupID
    int tig = lane & 3;          // thread-in-group

    float c[2][8][4];
    #pragma unroll
    for (int m = 0; m < 2; ++m)
        #pragma unroll
        for (int n = 0; n < 8; ++n)
            { c[m][n][0]=0.f; c[m][n][1]=0.f; c[m][n][2]=0.f; c[m][n][3]=0.f; }

    #pragma unroll
    for (int ks = 0; ks < 8; ++ks) {
        int c4a = 2 * ks, c4b = 2 * ks + 1;
        float a[2][4];
        #pragma unroll
        for (int m = 0; m < 2; ++m) {
            int r0 = wi * 32 + m * 16 + g;
            int r1 = r0 + 8;
            int x0 = (r0 & 7);
            a[m][0] = xi[(r0 << 6) + ((c4a ^ x0) << 2) + tig];
            a[m][2] = xi[(r0 << 6) + ((c4b ^ x0) << 2) + tig];
            a[m][1] = xi[(r1 << 6) + ((c4a ^ x0) << 2) + tig];
            a[m][3] = xi[(r1 << 6) + ((c4b ^ x0) << 2) + tig];
        }
        float bf[8][2];
        #pragma unroll
        for (int n = 0; n < 8; ++n) {
            int jr = wj * 64 + n * 8 + g;
            int xo = (jr & 7);
            bf[n][0] = xj[(jr << 6) + ((c4a ^ xo) << 2) + tig];
            bf[n][1] = xj[(jr << 6) + ((c4b ^ xo) << 2) + tig];
        }
        #pragma unroll
        for (int m = 0; m < 2; ++m)
            #pragma unroll
            for (int n = 0; n < 8; ++n)
                mma_tf32(c[m][n], a[m], bf[n]);
    }

    // epilogue: exp + masked row sums + (off-diag) col sums, fixed order
    signed char yj[16];
    #pragma unroll
    for (int n = 0; n < 8; ++n) {
        int col = wj * 64 + n * 8 + tig * 2;
        yj[2*n]   = ysj[col];
        yj[2*n+1] = ysj[col + 1];
    }
    float cd0[8], cd1[8], cp0[8], cp1[8];
    #pragma unroll
    for (int n = 0; n < 8; ++n) { cd0[n]=0.f; cd1[n]=0.f; cp0[n]=0.f; cp1[n]=0.f; }

    #pragma unroll
    for (int m = 0; m < 2; ++m) {
        int r0 = wi * 32 + m * 16 + g;
        int r1 = r0 + 8;
        int y0 = ysi[r0], y1 = ysi[r1];
        float d0 = 0.f, p0 = 0.f, d1 = 0.f, p1 = 0.f;
        #pragma unroll
        for (int n = 0; n < 8; ++n) {
            int col = wj * 64 + n * 8 + tig * 2;
            float e00 = ex2f(fmaf(c[m][n][0], C1_, C0_));
            float e01 = ex2f(fmaf(c[m][n][1], C1_, C0_));
            float e10 = ex2f(fmaf(c[m][n][2], C1_, C0_));
            float e11 = ex2f(fmaf(c[m][n][3], C1_, C0_));
            if (diagT) {
                if (r0 == col)     e00 = 0.f;
                if (r0 == col + 1) e01 = 0.f;
                if (r1 == col)     e10 = 0.f;
                if (r1 == col + 1) e11 = 0.f;
            }
            bool q00 = (y0 == yj[2*n]), q01 = (y0 == yj[2*n+1]);
            bool q10 = (y1 == yj[2*n]), q11 = (y1 == yj[2*n+1]);
            d0 += e00 + e01;
            d1 += e10 + e11;
            p0 += (q00 ? e00 : 0.f) + (q01 ? e01 : 0.f);
            p1 += (q10 ? e10 : 0.f) + (q11 ? e11 : 0.f);
            if (!diagT) {
                cd0[n] += e00 + e10;
                cd1[n] += e01 + e11;
                cp0[n] += (q00 ? e00 : 0.f) + (q10 ? e10 : 0.f);
                cp1[n] += (q01 ? e01 : 0.f) + (q11 ? e11 : 0.f);
            }
        }
        #pragma unroll
        for (int o = 1; o <= 2; o <<= 1) {
            d0 += __shfl_xor_sync(0xFFFFFFFFu, d0, o);
            p0 += __shfl_xor_sync(0xFFFFFFFFu, p0, o);
            d1 += __shfl_xor_sync(0xFFFFFFFFu, d1, o);
            p1 += __shfl_xor_sync(0xFFFFFFFFu, p1, o);
        }
        if (tig == 0) {
            rowd[r0][wj] = d0; rowp[r0][wj] = p0;
            rowd[r1][wj] = d1; rowp[r1][wj] = p1;
        }
    }

    if (!diagT) {
        #pragma unroll
        for (int n = 0; n < 8; ++n) {
            #pragma unroll
            for (int o = 4; o <= 16; o <<= 1) {
                cd0[n] += __shfl_xor_sync(0xFFFFFFFFu, cd0[n], o);
                cd1[n] += __shfl_xor_sync(0xFFFFFFFFu, cd1[n], o);
                cp0[n] += __shfl_xor_sync(0xFFFFFFFFu, cp0[n], o);
                cp1[n] += __shfl_xor_sync(0xFFFFFFFFu, cp1[n], o);
            }
        }
        if (lane < 4) {          // g == 0, tig == lane
            #pragma unroll
            for (int n = 0; n < 8; ++n) {
                int col = wj * 64 + n * 8 + lane * 2;
                cold[col][wi]     = cd0[n]; colp[col][wi]     = cp0[n];
                cold[col + 1][wi] = cd1[n]; colp[col + 1][wi] = cp1[n];
            }
        }
    }
    __syncthreads();
    if (t < 128) {
        int gi = b * K_ + it * 128 + t;
        g_d [gi * NJT + jt] = rowd[t][0] + rowd[t][1];
        g_pp[gi * NJT + jt] = rowp[t][0] + rowp[t][1];
        if (!diagT) {
            int gj = b * K_ + jt * 128 + t;
            g_d [gj * NJT + it] = ((cold[t][0] + cold[t][1]) + (cold[t][2] + cold[t][3]));
            g_pp[gj * NJT + it] = ((colp[t][0] + colp[t][1]) + (colp[t][2] + colp[t][3]));
        }
    }
}

// -------- per-row loss + per-image reduce; last block writes final scalar ---
__global__ void __launch_bounds__(256) rowloss_kernel(float* out) {
    int b = blockIdx.x, t = threadIdx.x;
    float ls = 0.0f; int cnt = 0;
    for (int i = t; i < K_; i += 256) {
        int yi = g_ys[b * K_ + i];
        float dv = 0.0f, pv = 0.0f;
        #pragma unroll
        for (int js = 0; js < NJT; ++js) {
            dv += g_d [(b * K_ + i) * NJT + js];
            pv += g_pp[(b * K_ + i) * NJT + js];
        }
        if (yi == 1 && pv > 0.0f) {
            ls += logf(fmaxf(dv, 1e-8f)) - logf(fmaxf(pv, 1e-8f));
            cnt++;
        }
    }
    __shared__ float ss[256];
    __shared__ int   sc[256];
    ss[t] = ls; sc[t] = cnt;
    __syncthreads();
    for (int o = 128; o; o >>= 1) {
        if (t < o) { ss[t] += ss[t + o]; sc[t] += sc[t + o]; }
        __syncthreads();
    }
    if (t == 0) { g_loss_sum[b] = ss[0]; g_valid[b] = sc[0]; }
    __syncthreads();
    __shared__ int lastFlag;
    if (t == 0) {
        __threadfence();
        lastFlag = (atomicAdd(&g_rldone, 1u) == (unsigned)(B_ - 1));
    }
    __syncthreads();
    if (lastFlag && t == 0) {
        float s = 0.0f;
        for (int bb = 0; bb < B_; ++bb) {        // fixed order -> deterministic
            int v = g_valid[bb]; if (v < 1) v = 1;
            s += g_loss_sum[bb] / (float)v;
        }
        out[0] = s / (float)B_;
    }
}

// -------- launch --------
extern "C" void kernel_launch(void* const* d_in, const int* in_sizes, int n_in,
                              void* d_out, int out_size) {
    const float* feats  = (const float*)d_in[0];
    const int*   labels = (const int*)d_in[1];

    // Derive JAX keys host-side (deterministic; baked into graph as kernel args).
    KeyArg ka;
    uint32_t out16[16];
    for (int j = 0; j < 8; ++j)
        tf2x32(0u, 1u, (uint32_t)j, (uint32_t)(8 + j), out16[j], out16[8 + j]);
    for (int b = 0; b < B_; ++b) {
        uint32_t kb0 = out16[2 * b], kb1 = out16[2 * b + 1];
        uint32_t o6[6];
        for (int j = 0; j < 3; ++j)
            tf2x32(kb0, kb1, (uint32_t)j, (uint32_t)(3 + j), o6[j], o6[3 + j]);
        ka.k[b][0][0] = o6[0]; ka.k[b][0][1] = o6[1];   // k1 -> fg pick
        ka.k[b][1][0] = o6[2]; ka.k[b][1][1] = o6[3];   // k2 -> ring pick
        ka.k[b][2][0] = o6[4]; ka.k[b][2][1] = o6[5];   // k3 -> bg pick
    }

    // 64 KB dynamic smem opt-in (idempotent; one-shot; graph-safe)
    static_assert(2 * 128 * 64 * sizeof(float) == 65536, "smem size");
    static bool s_attr_done = false;
    if (!s_attr_done) {
        cudaFuncSetAttribute(loss_mma_kernel,
                             cudaFuncAttributeMaxDynamicSharedMemorySize, 65536);
        s_attr_done = true;
    }

    mask_kernel<<<dim3(8, B_), 256>>>(labels);
    hash_hist_kernel<<<dim3(NG, 32), 256>>>(ka);
    emit_kernel<<<dim3(NG, 4), 256>>>();
    gather_kernel<<<(B_ * K_ * 32 + 255) / 256, 256>>>(feats);
    loss_mma_kernel<<<dim3(NTILES, B_), 256, 65536>>>();
    rowloss_kernel<<<B_, 256>>>((float*)d_out);
}

// round 16
// speedup vs baseline: 1.4603x; 1.3924x over previous
#include <cuda_runtime.h>
#include <cstdint>
#include <math.h>

#define B_ 8
#define C_ 64
#define H_ 256
#define W_ 256
#define P_ (H_*W_)
#define K_ 2048
#define NFG 1024
#define NHARD 768
#define NRAND 256
#define NG 24              // B_ * 3 picks
#define NJT 16             // j-tiles per row (2048/128)
#define NFT 8              // fg tiles (rows 0..1023)
#define NTILES 100         // upper-triangle tiles with it < NFT
#define CAPMAX 8192
#define LOCCAP 1024
#define BCMAX 512
// exp((c-1)/T) = 2^(c*C1 + C0),  C1 = log2(e)/T
#define C1_ 20.609929155555663f
#define C0_ (-20.609929155555663f)

// -------- scratch (static __device__, no allocations) --------
__device__ uint32_t g_fgbm [B_*2048];           // 256 rows x 8 words per image
__device__ uint32_t g_dilbm[B_*2048];
__device__ int g_mpart[B_][8][3];               // pool-count partials (no atomics)
__device__ unsigned int g_hist[NG][2048];
__device__ int g_bstar[NG];
__device__ int g_r[NG];
__device__ unsigned long long g_cap[NG][CAPMAX]; // captured (value,idx) keys
__device__ unsigned long long g_cand[NG][BCMAX];
__device__ int g_ccnt[NG];
__device__ int g_ocnt[NG];
__device__ int g_bccnt[NG];
__device__ unsigned int g_hdone[NG];
__device__ unsigned int g_edone[NG];
__device__ unsigned int g_rldone;
__device__ int   g_idx[B_*K_];
__device__ float g_fsn[B_*K_*C_];               // tf32-rounded normalized feats
__device__ float g_d [B_*K_*NJT];               // deterministic partials (fg rows only)
__device__ float g_loss_sum[B_];
__device__ int   g_valid[B_];

#define NZERO (NG*2048 + 5*NG + 1)

// -------- small PTX helpers --------
__device__ __forceinline__ float ex2f(float x) {
    float y; asm("ex2.approx.f32 %0, %1;" : "=f"(y) : "f"(x)); return y;
}
__device__ __forceinline__ float to_tf32(float x) {
    uint32_t y; asm("cvt.rna.tf32.f32 %0, %1;" : "=r"(y) : "f"(x));
    return __uint_as_float(y);
}
__device__ __forceinline__ void mma_tf32(float c[4], const float a[4], const float b[2]) {
    asm volatile(
        "mma.sync.aligned.m16n8k8.row.col.f32.tf32.tf32.f32 "
        "{%0,%1,%2,%3}, {%4,%5,%6,%7}, {%8,%9}, {%0,%1,%2,%3};"
        : "+f"(c[0]), "+f"(c[1]), "+f"(c[2]), "+f"(c[3])
        : "r"(__float_as_uint(a[0])), "r"(__float_as_uint(a[1])),
          "r"(__float_as_uint(a[2])), "r"(__float_as_uint(a[3])),
          "r"(__float_as_uint(b[0])), "r"(__float_as_uint(b[1])));
}

// -------- Threefry-2x32 (matches JAX threefry2x32 exactly) --------
__host__ __device__ inline void tf2x32(uint32_t k0, uint32_t k1,
                                       uint32_t x0, uint32_t x1,
                                       uint32_t& o0, uint32_t& o1) {
    uint32_t ks2 = k0 ^ k1 ^ 0x1BD11BDAu;
    x0 += k0; x1 += k1;
#define RR(r) { x0 += x1; x1 = (x1 << r) | (x1 >> (32 - r)); x1 ^= x0; }
    RR(13) RR(15) RR(26) RR(6)  x0 += k1;  x1 += ks2 + 1u;
    RR(17) RR(29) RR(16) RR(24) x0 += ks2; x1 += k0  + 2u;
    RR(13) RR(15) RR(26) RR(6)  x0 += k0;  x1 += k1  + 3u;
    RR(17) RR(29) RR(16) RR(24) x0 += k1;  x1 += ks2 + 4u;
    RR(13) RR(15) RR(26) RR(6)  x0 += ks2; x1 += k0  + 5u;
#undef RR
    o0 = x0; o1 = x1;
}

// mask bit test for pick from bitmap words
__device__ __forceinline__ bool inmask_bits(int pick, uint32_t fgw, uint32_t dlw, int bp) {
    int fg = (fgw >> bp) & 1, dl = (dlw >> bp) & 1;
    return (pick == 0) ? fg : (pick == 1) ? (dl && !fg) : !dl;   // fg => dl
}

// -------- ONE mask kernel: bit-packed 21x21 dilation + zeroing + counts -----
__global__ void __launch_bounds__(256) mask_kernel(const int* __restrict__ labels) {
    int b = blockIdx.y, rg = blockIdx.x;
    int t = threadIdx.x, w = t >> 5, l = t & 31;

    int gtid = (b * 8 + rg) * 256 + t;
    for (int z = gtid; z < NZERO; z += 64 * 256) {
        if (z < NG*2048) { ((unsigned int*)g_hist)[z] = 0u; continue; }
        int r = z - NG*2048;
        if      (r < NG)    g_ccnt[r] = 0;
        else if (r < 2*NG)  g_ocnt[r - NG] = 0;
        else if (r < 3*NG)  g_bccnt[r - 2*NG] = 0;
        else if (r < 4*NG)  g_hdone[r - 3*NG] = 0u;
        else if (r < 5*NG)  g_edone[r - 4*NG] = 0u;
        else                g_rldone = 0u;
    }

    __shared__ uint32_t sfg[52][8], srd[52][8];
    int r0 = rg * 32;
    for (int r = w; r < 52; r += 8) {                 // uniform per warp
        int gr = r0 - 10 + r;
        bool valid = (gr >= 0 && gr < H_);
        uint32_t wd[8];
        #pragma unroll
        for (int i = 0; i < 8; ++i) {
            int bit = 0;
            if (valid) bit = (labels[b * P_ + gr * W_ + i * 32 + l] == 1);
            wd[i] = __ballot_sync(0xFFFFFFFFu, bit);
        }
        if (l < 8) {
            uint32_t prev = (l > 0) ? wd[l - 1] : 0u;
            uint32_t cur  = wd[l];
            uint32_t nxt  = (l < 7) ? wd[l + 1] : 0u;
            uint32_t res = cur;
            #pragma unroll
            for (int s = 1; s <= 10; ++s)
                res |= ((cur << s) | (prev >> (32 - s)))
                     | ((cur >> s) | (nxt  << (32 - s)));
            sfg[r][l] = cur;
            srd[r][l] = res;
        }
    }
    __syncthreads();
    int k = t >> 3, wi = t & 7;
    uint32_t dil = 0;
    #pragma unroll
    for (int dr = 0; dr < 21; ++dr) dil |= srd[k + dr][wi];
    uint32_t fg = sfg[k + 10][wi];
    int grow = r0 + k;
    g_fgbm [b * 2048 + grow * 8 + wi] = fg;
    g_dilbm[b * 2048 + grow * 8 + wi] = dil;

    int c0 = __popc(fg), c1 = __popc(dil & ~fg), c2 = __popc(~dil);
    #pragma unroll
    for (int o = 16; o; o >>= 1) {
        c0 += __shfl_xor_sync(0xFFFFFFFFu, c0, o);
        c1 += __shfl_xor_sync(0xFFFFFFFFu, c1, o);
        c2 += __shfl_xor_sync(0xFFFFFFFFu, c2, o);
    }
    __shared__ int pw[8][3];
    if (l == 0) { pw[w][0] = c0; pw[w][1] = c1; pw[w][2] = c2; }
    __syncthreads();
    if (t == 0) {
        int s0 = 0, s1 = 0, s2 = 0;
        #pragma unroll
        for (int q = 0; q < 8; ++q) { s0 += pw[q][0]; s1 += pw[q][1]; s2 += pw[q][2]; }
        g_mpart[b][rg][0] = s0; g_mpart[b][rg][1] = s1; g_mpart[b][rg][2] = s2;
    }
}

// -------- selection pass: MASK-FIRST hash + hist(subset) + CAPTURE ----------
struct KeyArg { uint32_t k[B_][3][2]; };

__global__ void __launch_bounds__(256) hash_hist_kernel(KeyArg ka) {
    int g = blockIdx.x, chunk = blockIdx.y;
    int b = g / 3, pick = g % 3;
    int n = (pick == 0) ? NFG : (pick == 1) ? NHARD : NRAND;
    uint32_t k0 = ka.k[b][pick][0], k1 = ka.k[b][pick][1];
    int t = threadIdx.x;
    int m = 0;
    #pragma unroll
    for (int q = 0; q < 8; ++q) m += g_mpart[b][q][pick];
    if (m < 1) m = 1;
    int span = (int)(((long long)6 * n * 2048 + m - 1) / m);   // ceil(6n*2048/m)
    if (span > 2048) span = 2048;
    int bfloor = 2048 - span;
    const uint32_t* fgb = g_fgbm  + b * 2048;
    const uint32_t* dlb = g_dilbm + b * 2048;

    __shared__ unsigned long long loc[LOCCAP];
    __shared__ int lcnt;
    if (t == 0) lcnt = 0;
    __syncthreads();

    for (int kk = 0; kk < 4; ++kk) {
        int p0 = chunk * 1024 + kk * 256 + t;
        int wi0 = p0 >> 5, bp = p0 & 31;
        bool m0 = inmask_bits(pick, fgb[wi0],        dlb[wi0],        bp);
        bool m1 = inmask_bits(pick, fgb[wi0 + 1024], dlb[wi0 + 1024], bp);
        if (!m0 && !m1) continue;
        uint32_t o0, o1;
        tf2x32(k0, k1, (uint32_t)p0, (uint32_t)(p0 + 32768), o0, o1);
        #pragma unroll
        for (int hh = 0; hh < 2; ++hh) {
            bool mm = hh ? m1 : m0;
            if (!mm) continue;
            int p = p0 + hh * 32768;
            uint32_t u = hh ? o1 : o0;
            int bin = (int)(u >> 21);
            if (bin < bfloor) continue;
            atomicAdd(&g_hist[g][bin], 1u);
            unsigned long long key = ((unsigned long long)(u >> 9) << 16)
                                   | (unsigned long long)(0xFFFFu - (uint32_t)p);
            int pos = atomicAdd(&lcnt, 1);            // SMEM atomic
            if (pos < LOCCAP) loc[pos] = key;
            else {
                int gp = atomicAdd(&g_ccnt[g], 1);
                if (gp < CAPMAX) g_cap[g][gp] = key;
            }
        }
    }
    __syncthreads();
    int c = lcnt < LOCCAP ? lcnt : LOCCAP;
    __shared__ int sbase;
    if (t == 0) sbase = atomicAdd(&g_ccnt[g], c);          // ONE reservation/block
    __syncthreads();
    for (int ci = t; ci < c; ci += 256) {
        int gp = sbase + ci;
        if (gp < CAPMAX) g_cap[g][gp] = loc[ci];
    }
    __syncthreads();
    __shared__ int lastFlag;
    if (t == 0) {
        __threadfence();
        lastFlag = (atomicAdd(&g_hdone[g], 1u) == 31u);
    }
    __syncthreads();
    if (!lastFlag) return;

    // ---- fused scan: parallel prefix over 256 8-bin segments (descending) --
    unsigned int hv[8], s8 = 0;
    #pragma unroll
    for (int k = 0; k < 8; ++k) { hv[k] = g_hist[g][2047 - (t * 8 + k)]; s8 += hv[k]; }
    __shared__ unsigned int part[256];
    part[t] = s8;
    __syncthreads();
    #pragma unroll
    for (int off = 1; off < 256; off <<= 1) {
        unsigned int v = (t >= off) ? part[t - off] : 0u;
        __syncthreads();
        part[t] += v;
        __syncthreads();
    }
    int incl = (int)part[t];
    int before = incl - (int)s8;
    if (before < n && incl >= n) {          // exactly one owner thread
        int cum = before, bstar = 0, above = before;
        #pragma unroll
        for (int k = 0; k < 8; ++k) {
            int q = 2047 - (t * 8 + k);
            int hh = (int)hv[k];
            if (cum + hh >= n) { bstar = q; above = cum; break; }
            cum += hh;
        }
        g_bstar[g] = bstar;
        g_r[g] = n - above;
    }
}

// -------- tiny emit from compact list (grid NG x 4, 256 thr) --------
__global__ void __launch_bounds__(256) emit_kernel() {
    int g = blockIdx.x, quarter = blockIdx.y;
    int b = g / 3, pick = g % 3;
    int base = b * K_ + ((pick == 0) ? 0 : (pick == 1) ? NFG : (NFG + NHARD));
    int bstar = g_bstar[g];
    int t = threadIdx.x, lane = t & 31;
    int cnt = g_ccnt[g]; if (cnt > CAPMAX) cnt = CAPMAX;

    #pragma unroll
    for (int it = 0; it < 8; ++it) {                  // fixed trip count: warp-uniform
        int ci = quarter * 2048 + it * 256 + t;
        bool valid = (ci < cnt);
        unsigned long long v = valid ? g_cap[g][ci] : 0ull;
        int bin = (int)(v >> 28);
        bool win = valid && (bin > bstar);
        unsigned int mk = __ballot_sync(0xFFFFFFFFu, win);
        if (mk) {
            int ldr = __ffs(mk) - 1;
            int sb_ = 0;
            if (lane == ldr) sb_ = atomicAdd(&g_ocnt[g], __popc(mk));
            sb_ = __shfl_sync(0xFFFFFFFFu, sb_, ldr);
            if (win)
                g_idx[base + sb_ + __popc(mk & ((1u << lane) - 1u))]
                    = 0xFFFF - (int)(v & 0xFFFFull);
        }
        bool bnd = valid && (bin == bstar);
        if (bnd) {
            int c2 = atomicAdd(&g_bccnt[g], 1);
            if (c2 < BCMAX) g_cand[g][c2] = v;
        }
    }
    __syncthreads();
    __shared__ int lastFlag;
    if (t == 0) {
        __threadfence();
        lastFlag = (atomicAdd(&g_edone[g], 1u) == 3u);
    }
    __syncthreads();
    if (!lastFlag) return;

    // ---- boundary-bin rank select ----
    int c = g_bccnt[g]; if (c > BCMAX) c = BCMAX;
    int r = g_r[g];
    __shared__ unsigned long long cd[BCMAX];
    for (int ci = t; ci < c; ci += 256) cd[ci] = g_cand[g][ci];
    __syncthreads();
    for (int ci = t; ci < c; ci += 256) {
        unsigned long long v = cd[ci];
        int rank = 0;
        for (int q = 0; q < c; ++q) rank += (cd[q] > v);
        if (rank < r) {
            int slot = atomicAdd(&g_ocnt[g], 1);
            g_idx[base + slot] = 0xFFFF - (int)(v & 0xFFFFull);
        }
    }
}

// -------- gather + L2-normalize + tf32 round (one warp per sample) --------
__global__ void gather_kernel(const float* __restrict__ feats) {
    int gw   = (blockIdx.x * blockDim.x + threadIdx.x) >> 5;
    int lane = threadIdx.x & 31;
    if (gw >= B_ * K_) return;
    int b = gw / K_;
    int p = g_idx[gw];
    const float* f = feats + (size_t)b * C_ * P_ + p;
    float v0 = f[(size_t)lane * P_];
    float v1 = f[(size_t)(lane + 32) * P_];
    float ss = v0 * v0 + v1 * v1;
    #pragma unroll
    for (int o = 16; o; o >>= 1) ss += __shfl_xor_sync(0xFFFFFFFFu, ss, o);
    float inv = 1.0f / fmaxf(sqrtf(ss), 1e-12f);
    float* out = g_fsn + (size_t)gw * C_;
    out[lane]      = to_tf32(v0 * inv);   // tf32-matmul input semantics
    out[lane + 32] = to_tf32(v1 * inv);
    // ys is implicit: rows [0,1024) are fg (label 1), rest label 0
}

// -------- fused Gram (tf32 mma): only tiles with fg rows (it < 8) -----------
// grid (100, b=8), 256 thr = 8 warps (4 i-warps x 2 j-warps)
// labels constant per tile: pv = sum of jt<8 partials, dv = all 16.
__global__ void __launch_bounds__(256, 2) loss_mma_kernel() {
    extern __shared__ float smem[];
    float* xi = smem;            // 128 x 64
    float* xj = smem + 8192;     // 128 x 64
    __shared__ float rowd[128][2];
    __shared__ float cold[128][4];

    int b = blockIdx.y;
    int u = blockIdx.x;
    int it = 0;
    while (u >= NJT - it) { u -= NJT - it; ++it; }   // it in [0,8) for u<100
    int jt = it + u;
    bool diagT = (it == jt);
    bool needCol = (!diagT && jt < NFT);             // jt rows fg -> need col sums
    int t = threadIdx.x;

    const float4* src_i = (const float4*)(g_fsn + ((size_t)b * K_ + it * 128) * C_);
    const float4* src_j = (const float4*)(g_fsn + ((size_t)b * K_ + jt * 128) * C_);
    for (int q = t; q < 2048; q += 256) {
        int row = q >> 4, c4 = q & 15;
        int dst = (row << 6) + ((c4 ^ (row & 7)) << 2);
        *(float4*)(xi + dst) = src_i[q];
        *(float4*)(xj + dst) = src_j[q];
    }
    __syncthreads();

    int w    = t >> 5;
    int lane = t & 31;
    int wi = w >> 1;             // 0..3 : i-strip of 32 rows
    int wj = w & 1;              // 0..1 : j-strip of 64 cols
    int g   = lane >> 2;         // groupID
    int tig = lane & 3;          // thread-in-group

    float c[2][8][4];
    #pragma unroll
    for (int m = 0; m < 2; ++m)
        #pragma unroll
        for (int n = 0; n < 8; ++n)
            { c[m][n][0]=0.f; c[m][n][1]=0.f; c[m][n][2]=0.f; c[m][n][3]=0.f; }

    #pragma unroll
    for (int ks = 0; ks < 8; ++ks) {
        int c4a = 2 * ks, c4b = 2 * ks + 1;
        float a[2][4];
        #pragma unroll
        for (int m = 0; m < 2; ++m) {
            int r0 = wi * 32 + m * 16 + g;
            int r1 = r0 + 8;
            int x0 = (r0 & 7);
            a[m][0] = xi[(r0 << 6) + ((c4a ^ x0) << 2) + tig];
            a[m][2] = xi[(r0 << 6) + ((c4b ^ x0) << 2) + tig];
            a[m][1] = xi[(r1 << 6) + ((c4a ^ x0) << 2) + tig];
            a[m][3] = xi[(r1 << 6) + ((c4b ^ x0) << 2) + tig];
        }
        float bf[8][2];
        #pragma unroll
        for (int n = 0; n < 8; ++n) {
            int jr = wj * 64 + n * 8 + g;
            int xo = (jr & 7);
            bf[n][0] = xj[(jr << 6) + ((c4a ^ xo) << 2) + tig];
            bf[n][1] = xj[(jr << 6) + ((c4b ^ xo) << 2) + tig];
        }
        #pragma unroll
        for (int m = 0; m < 2; ++m)
            #pragma unroll
            for (int n = 0; n < 8; ++n)
                mma_tf32(c[m][n], a[m], bf[n]);
    }

    // epilogue: exp + row sums (+ col sums when jt is fg), fixed order
    float cd0[8], cd1[8];
    #pragma unroll
    for (int n = 0; n < 8; ++n) { cd0[n] = 0.f; cd1[n] = 0.f; }

    #pragma unroll
    for (int m = 0; m < 2; ++m) {
        int r0 = wi * 32 + m * 16 + g;
        int r1 = r0 + 8;
        float d0 = 0.f, d1 = 0.f;
        #pragma unroll
        for (int n = 0; n < 8; ++n) {
            int col = wj * 64 + n * 8 + tig * 2;
            float e00 = ex2f(fmaf(c[m][n][0], C1_, C0_));
            float e01 = ex2f(fmaf(c[m][n][1], C1_, C0_));
            float e10 = ex2f(fmaf(c[m][n][2], C1_, C0_));
            float e11 = ex2f(fmaf(c[m][n][3], C1_, C0_));
            if (diagT) {
                if (r0 == col)     e00 = 0.f;
                if (r0 == col + 1) e01 = 0.f;
                if (r1 == col)     e10 = 0.f;
                if (r1 == col + 1) e11 = 0.f;
            }
            d0 += e00 + e01;
            d1 += e10 + e11;
            if (needCol) {
                cd0[n] += e00 + e10;
                cd1[n] += e01 + e11;
            }
        }
        #pragma unroll
        for (int o = 1; o <= 2; o <<= 1) {
            d0 += __shfl_xor_sync(0xFFFFFFFFu, d0, o);
            d1 += __shfl_xor_sync(0xFFFFFFFFu, d1, o);
        }
        if (tig == 0) {
            rowd[r0][wj] = d0;
            rowd[r1][wj] = d1;
        }
    }

    if (needCol) {
        #pragma unroll
        for (int n = 0; n < 8; ++n) {
            #pragma unroll
            for (int o = 4; o <= 16; o <<= 1) {
                cd0[n] += __shfl_xor_sync(0xFFFFFFFFu, cd0[n], o);
                cd1[n] += __shfl_xor_sync(0xFFFFFFFFu, cd1[n], o);
            }
        }
        if (lane < 4) {          // g == 0, tig == lane
            #pragma unroll
            for (int n = 0; n < 8; ++n) {
                int col = wj * 64 + n * 8 + lane * 2;
                cold[col][wi]     = cd0[n];
                cold[col + 1][wi] = cd1[n];
            }
        }
    }
    __syncthreads();
    if (t < 128) {
        int gi = b * K_ + it * 128 + t;
        g_d[gi * NJT + jt] = rowd[t][0] + rowd[t][1];
        if (needCol) {
            int gj = b * K_ + jt * 128 + t;
            g_d[gj * NJT + it] = ((cold[t][0] + cold[t][1]) + (cold[t][2] + cold[t][3]));
        }
    }
}

// -------- per-row loss (fg rows only) + per-image reduce --------
__global__ void __launch_bounds__(256) rowloss_kernel(float* out) {
    int b = blockIdx.x, t = threadIdx.x;
    float ls = 0.0f; int cnt = 0;
    for (int i = t; i < NFG; i += 256) {
        // pv = fg-column partials (js<8); dv continues the SAME chain (js<16)
        float pv = 0.0f;
        #pragma unroll
        for (int js = 0; js < NFT; ++js) pv += g_d[(b * K_ + i) * NJT + js];
        float dv = pv;
        #pragma unroll
        for (int js = NFT; js < NJT; ++js) dv += g_d[(b * K_ + i) * NJT + js];
        if (pv > 0.0f) {
            ls += logf(fmaxf(dv, 1e-8f)) - logf(fmaxf(pv, 1e-8f));
            cnt++;
        }
    }
    __shared__ float ss[256];
    __shared__ int   sc[256];
    ss[t] = ls; sc[t] = cnt;
    __syncthreads();
    for (int o = 128; o; o >>= 1) {
        if (t < o) { ss[t] += ss[t + o]; sc[t] += sc[t + o]; }
        __syncthreads();
    }
    if (t == 0) { g_loss_sum[b] = ss[0]; g_valid[b] = sc[0]; }
    __syncthreads();
    __shared__ int lastFlag;
    if (t == 0) {
        __threadfence();
        lastFlag = (atomicAdd(&g_rldone, 1u) == (unsigned)(B_ - 1));
    }
    __syncthreads();
    if (lastFlag && t == 0) {
        float s = 0.0f;
        for (int bb = 0; bb < B_; ++bb) {        // fixed order -> deterministic
            int v = g_valid[bb]; if (v < 1) v = 1;
            s += g_loss_sum[bb] / (float)v;
        }
        out[0] = s / (float)B_;
    }
}

// -------- launch --------
extern "C" void kernel_launch(void* const* d_in, const int* in_sizes, int n_in,
                              void* d_out, int out_size) {
    const float* feats  = (const float*)d_in[0];
    const int*   labels = (const int*)d_in[1];

    // Derive JAX keys host-side (deterministic; baked into graph as kernel args).
    KeyArg ka;
    uint32_t out16[16];
    for (int j = 0; j < 8; ++j)
        tf2x32(0u, 1u, (uint32_t)j, (uint32_t)(8 + j), out16[j], out16[8 + j]);
    for (int b = 0; b < B_; ++b) {
        uint32_t kb0 = out16[2 * b], kb1 = out16[2 * b + 1];
        uint32_t o6[6];
        for (int j = 0; j < 3; ++j)
            tf2x32(kb0, kb1, (uint32_t)j, (uint32_t)(3 + j), o6[j], o6[3 + j]);
        ka.k[b][0][0] = o6[0]; ka.k[b][0][1] = o6[1];   // k1 -> fg pick
        ka.k[b][1][0] = o6[2]; ka.k[b][1][1] = o6[3];   // k2 -> ring pick
        ka.k[b][2][0] = o6[4]; ka.k[b][2][1] = o6[5];   // k3 -> bg pick
    }

    // 64 KB dynamic smem opt-in (idempotent; one-shot; graph-safe)
    static_assert(2 * 128 * 64 * sizeof(float) == 65536, "smem size");
    static bool s_attr_done = false;
    if (!s_attr_done) {
        cudaFuncSetAttribute(loss_mma_kernel,
                             cudaFuncAttributeMaxDynamicSharedMemorySize, 65536);
        s_attr_done = true;
    }

    mask_kernel<<<dim3(8, B_), 256>>>(labels);
    hash_hist_kernel<<<dim3(NG, 32), 256>>>(ka);
    emit_kernel<<<dim3(NG, 4), 256>>>();
    gather_kernel<<<(B_ * K_ * 32 + 255) / 256, 256>>>(feats);
    loss_mma_kernel<<<dim3(NTILES, B_), 256, 65536>>>();
    rowloss_kernel<<<B_, 256>>>((float*)d_out);
}

// round 17
// speedup vs baseline: 1.4941x; 1.0232x over previous
#include <cuda_runtime.h>
#include <cstdint>
#include <math.h>

#define B_ 8
#define C_ 64
#define H_ 256
#define W_ 256
#define P_ (H_*W_)
#define K_ 2048
#define NFG 1024
#define NHARD 768
#define NRAND 256
#define NG 24              // B_ * 3 picks
#define NJT 16             // j-tiles per row (2048/128)
#define NFT 8              // fg tiles (rows 0..1023)
#define NTILES 100         // upper-triangle tiles with it < NFT
#define CAPMAX 8192
#define LOCCAP 1024
#define BCMAX 512
// exp((c-1)/T) = 2^(c*C1 + C0),  C1 = log2(e)/T
#define C1_ 20.609929155555663f
#define C0_ (-20.609929155555663f)

// -------- scratch (static __device__, no allocations) --------
__device__ uint32_t g_fgbm [B_*2048];           // 256 rows x 8 words per image
__device__ uint32_t g_dilbm[B_*2048];
__device__ int g_mpart[B_][8][3];               // pool-count partials (no atomics)
__device__ unsigned int g_hist[NG][2048];
__device__ unsigned long long g_cap[NG][CAPMAX]; // captured (value,idx) keys
__device__ int g_ccnt[NG];
__device__ unsigned int g_hdone[NG];
__device__ unsigned int g_rldone;
__device__ int   g_idx[B_*K_];
__device__ float g_fsn[B_*K_*C_];               // tf32-rounded normalized feats
__device__ float g_d [B_*K_*NJT];               // deterministic partials (fg rows only)
__device__ float g_loss_sum[B_];
__device__ int   g_valid[B_];

#define NZERO (NG*2048 + 2*NG + 1)

// -------- small PTX helpers --------
__device__ __forceinline__ float ex2f(float x) {
    float y; asm("ex2.approx.f32 %0, %1;" : "=f"(y) : "f"(x)); return y;
}
__device__ __forceinline__ float to_tf32(float x) {
    uint32_t y; asm("cvt.rna.tf32.f32 %0, %1;" : "=r"(y) : "f"(x));
    return __uint_as_float(y);
}
__device__ __forceinline__ void mma_tf32(float c[4], const float a[4], const float b[2]) {
    asm volatile(
        "mma.sync.aligned.m16n8k8.row.col.f32.tf32.tf32.f32 "
        "{%0,%1,%2,%3}, {%4,%5,%6,%7}, {%8,%9}, {%0,%1,%2,%3};"
        : "+f"(c[0]), "+f"(c[1]), "+f"(c[2]), "+f"(c[3])
        : "r"(__float_as_uint(a[0])), "r"(__float_as_uint(a[1])),
          "r"(__float_as_uint(a[2])), "r"(__float_as_uint(a[3])),
          "r"(__float_as_uint(b[0])), "r"(__float_as_uint(b[1])));
}

// -------- Threefry-2x32 (matches JAX threefry2x32 exactly) --------
__host__ __device__ inline void tf2x32(uint32_t k0, uint32_t k1,
                                       uint32_t x0, uint32_t x1,
                                       uint32_t& o0, uint32_t& o1) {
    uint32_t ks2 = k0 ^ k1 ^ 0x1BD11BDAu;
    x0 += k0; x1 += k1;
#define RR(r) { x0 += x1; x1 = (x1 << r) | (x1 >> (32 - r)); x1 ^= x0; }
    RR(13) RR(15) RR(26) RR(6)  x0 += k1;  x1 += ks2 + 1u;
    RR(17) RR(29) RR(16) RR(24) x0 += ks2; x1 += k0  + 2u;
    RR(13) RR(15) RR(26) RR(6)  x0 += k0;  x1 += k1  + 3u;
    RR(17) RR(29) RR(16) RR(24) x0 += k1;  x1 += ks2 + 4u;
    RR(13) RR(15) RR(26) RR(6)  x0 += ks2; x1 += k0  + 5u;
#undef RR
    o0 = x0; o1 = x1;
}

// mask bit test for pick from bitmap words
__device__ __forceinline__ bool inmask_bits(int pick, uint32_t fgw, uint32_t dlw, int bp) {
    int fg = (fgw >> bp) & 1, dl = (dlw >> bp) & 1;
    return (pick == 0) ? fg : (pick == 1) ? (dl && !fg) : !dl;   // fg => dl
}

// -------- ONE mask kernel: bit-packed 21x21 dilation + zeroing + counts -----
__global__ void __launch_bounds__(256) mask_kernel(const int* __restrict__ labels) {
    int b = blockIdx.y, rg = blockIdx.x;
    int t = threadIdx.x, w = t >> 5, l = t & 31;

    int gtid = (b * 8 + rg) * 256 + t;
    for (int z = gtid; z < NZERO; z += 64 * 256) {
        if (z < NG*2048) { ((unsigned int*)g_hist)[z] = 0u; continue; }
        int r = z - NG*2048;
        if      (r < NG)    g_ccnt[r] = 0;
        else if (r < 2*NG)  g_hdone[r - NG] = 0u;
        else                g_rldone = 0u;
    }

    __shared__ uint32_t sfg[52][8], srd[52][8];
    int r0 = rg * 32;
    for (int r = w; r < 52; r += 8) {                 // uniform per warp
        int gr = r0 - 10 + r;
        bool valid = (gr >= 0 && gr < H_);
        uint32_t wd[8];
        #pragma unroll
        for (int i = 0; i < 8; ++i) {
            int bit = 0;
            if (valid) bit = (labels[b * P_ + gr * W_ + i * 32 + l] == 1);
            wd[i] = __ballot_sync(0xFFFFFFFFu, bit);
        }
        if (l < 8) {
            uint32_t prev = (l > 0) ? wd[l - 1] : 0u;
            uint32_t cur  = wd[l];
            uint32_t nxt  = (l < 7) ? wd[l + 1] : 0u;
            uint32_t res = cur;
            #pragma unroll
            for (int s = 1; s <= 10; ++s)
                res |= ((cur << s) | (prev >> (32 - s)))
                     | ((cur >> s) | (nxt  << (32 - s)));
            sfg[r][l] = cur;
            srd[r][l] = res;
        }
    }
    __syncthreads();
    int k = t >> 3, wi = t & 7;
    uint32_t dil = 0;
    #pragma unroll
    for (int dr = 0; dr < 21; ++dr) dil |= srd[k + dr][wi];
    uint32_t fg = sfg[k + 10][wi];
    int grow = r0 + k;
    g_fgbm [b * 2048 + grow * 8 + wi] = fg;
    g_dilbm[b * 2048 + grow * 8 + wi] = dil;

    int c0 = __popc(fg), c1 = __popc(dil & ~fg), c2 = __popc(~dil);
    #pragma unroll
    for (int o = 16; o; o >>= 1) {
        c0 += __shfl_xor_sync(0xFFFFFFFFu, c0, o);
        c1 += __shfl_xor_sync(0xFFFFFFFFu, c1, o);
        c2 += __shfl_xor_sync(0xFFFFFFFFu, c2, o);
    }
    __shared__ int pw[8][3];
    if (l == 0) { pw[w][0] = c0; pw[w][1] = c1; pw[w][2] = c2; }
    __syncthreads();
    if (t == 0) {
        int s0 = 0, s1 = 0, s2 = 0;
        #pragma unroll
        for (int q = 0; q < 8; ++q) { s0 += pw[q][0]; s1 += pw[q][1]; s2 += pw[q][2]; }
        g_mpart[b][rg][0] = s0; g_mpart[b][rg][1] = s1; g_mpart[b][rg][2] = s2;
    }
}

// -------- ONE-kernel selection: mask-first hash + capture; last block
// does scan AND emit from the compact list (smem counters, no global atomics)
struct KeyArg { uint32_t k[B_][3][2]; };

__global__ void __launch_bounds__(256) select_kernel(KeyArg ka) {
    int g = blockIdx.x, chunk = blockIdx.y;
    int b = g / 3, pick = g % 3;
    int n = (pick == 0) ? NFG : (pick == 1) ? NHARD : NRAND;
    int base = b * K_ + ((pick == 0) ? 0 : (pick == 1) ? NFG : (NFG + NHARD));
    uint32_t k0 = ka.k[b][pick][0], k1 = ka.k[b][pick][1];
    int t = threadIdx.x;
    int m = 0;
    #pragma unroll
    for (int q = 0; q < 8; ++q) m += g_mpart[b][q][pick];
    if (m < 1) m = 1;
    int span = (int)(((long long)6 * n * 2048 + m - 1) / m);   // ceil(6n*2048/m)
    if (span > 2048) span = 2048;
    int bfloor = 2048 - span;
    const uint32_t* fgb = g_fgbm  + b * 2048;
    const uint32_t* dlb = g_dilbm + b * 2048;

    __shared__ unsigned long long loc[LOCCAP];
    __shared__ int lcnt;
    if (t == 0) lcnt = 0;
    __syncthreads();

    for (int kk = 0; kk < 4; ++kk) {
        int p0 = chunk * 1024 + kk * 256 + t;
        int wi0 = p0 >> 5, bp = p0 & 31;
        bool m0 = inmask_bits(pick, fgb[wi0],        dlb[wi0],        bp);
        bool m1 = inmask_bits(pick, fgb[wi0 + 1024], dlb[wi0 + 1024], bp);
        if (!m0 && !m1) continue;
        uint32_t o0, o1;
        tf2x32(k0, k1, (uint32_t)p0, (uint32_t)(p0 + 32768), o0, o1);
        #pragma unroll
        for (int hh = 0; hh < 2; ++hh) {
            bool mm = hh ? m1 : m0;
            if (!mm) continue;
            int p = p0 + hh * 32768;
            uint32_t u = hh ? o1 : o0;
            int bin = (int)(u >> 21);
            if (bin < bfloor) continue;
            atomicAdd(&g_hist[g][bin], 1u);
            // value desc, then index asc (top_k tie rule)
            unsigned long long key = ((unsigned long long)(u >> 9) << 16)
                                   | (unsigned long long)(0xFFFFu - (uint32_t)p);
            int pos = atomicAdd(&lcnt, 1);            // SMEM atomic
            if (pos < LOCCAP) loc[pos] = key;
            else {                                     // unexpected overflow
                int gp = atomicAdd(&g_ccnt[g], 1);
                if (gp < CAPMAX) g_cap[g][gp] = key;
            }
        }
    }
    __syncthreads();
    int c = lcnt < LOCCAP ? lcnt : LOCCAP;
    __shared__ int sbase;
    if (t == 0) sbase = atomicAdd(&g_ccnt[g], c);          // ONE reservation/block
    __syncthreads();
    for (int ci = t; ci < c; ci += 256) {
        int gp = sbase + ci;
        if (gp < CAPMAX) g_cap[g][gp] = loc[ci];
    }
    __syncthreads();
    __shared__ int lastFlag;
    if (t == 0) {
        __threadfence();
        lastFlag = (atomicAdd(&g_hdone[g], 1u) == 31u);
    }
    __syncthreads();
    if (!lastFlag) return;

    // ---- scan: parallel prefix over 256 8-bin segments (descending) ----
    __shared__ int s_bstar, s_r;
    unsigned int hv[8], s8 = 0;
    #pragma unroll
    for (int k = 0; k < 8; ++k) { hv[k] = g_hist[g][2047 - (t * 8 + k)]; s8 += hv[k]; }
    __shared__ unsigned int part[256];
    part[t] = s8;
    __syncthreads();
    #pragma unroll
    for (int off = 1; off < 256; off <<= 1) {
        unsigned int v = (t >= off) ? part[t - off] : 0u;
        __syncthreads();
        part[t] += v;
        __syncthreads();
    }
    int incl = (int)part[t];
    int before = incl - (int)s8;
    if (before < n && incl >= n) {          // exactly one owner thread
        int cum = before, bstar = 0, above = before;
        #pragma unroll
        for (int k = 0; k < 8; ++k) {
            int q = 2047 - (t * 8 + k);
            int hh = (int)hv[k];
            if (cum + hh >= n) { bstar = q; above = cum; break; }
            cum += hh;
        }
        s_bstar = bstar;
        s_r = n - above;
    }
    __shared__ unsigned long long bc[BCMAX];
    __shared__ int s_o, s_bc;
    if (t == 0) { s_o = 0; s_bc = 0; }
    __syncthreads();

    // ---- emit from compact capture list (block-local counters) ----
    int cnt = g_ccnt[g]; if (cnt > CAPMAX) cnt = CAPMAX;
    int bstar = s_bstar;
    for (int ci = t; ci < cnt; ci += 256) {
        unsigned long long v = g_cap[g][ci];
        int bin = (int)(v >> 28);           // (u>>9)>>12 == u>>21
        if (bin > bstar) {
            int slot = atomicAdd(&s_o, 1);
            g_idx[base + slot] = 0xFFFF - (int)(v & 0xFFFFull);
        } else if (bin == bstar) {
            int c2 = atomicAdd(&s_bc, 1);
            if (c2 < BCMAX) bc[c2] = v;
        }
    }
    __syncthreads();
    int cb = s_bc < BCMAX ? s_bc : BCMAX;
    int r = s_r;
    for (int ci = t; ci < cb; ci += 256) {
        unsigned long long v = bc[ci];
        int rank = 0;
        for (int q = 0; q < cb; ++q) rank += (bc[q] > v);
        if (rank < r) {
            int slot = atomicAdd(&s_o, 1);
            g_idx[base + slot] = 0xFFFF - (int)(v & 0xFFFFull);
        }
    }
}

// -------- gather + L2-normalize + tf32 round (one warp per sample) --------
__global__ void gather_kernel(const float* __restrict__ feats) {
    int gw   = (blockIdx.x * blockDim.x + threadIdx.x) >> 5;
    int lane = threadIdx.x & 31;
    if (gw >= B_ * K_) return;
    int b = gw / K_;
    int p = g_idx[gw];
    const float* f = feats + (size_t)b * C_ * P_ + p;
    float v0 = f[(size_t)lane * P_];
    float v1 = f[(size_t)(lane + 32) * P_];
    float ss = v0 * v0 + v1 * v1;
    #pragma unroll
    for (int o = 16; o; o >>= 1) ss += __shfl_xor_sync(0xFFFFFFFFu, ss, o);
    float inv = 1.0f / fmaxf(sqrtf(ss), 1e-12f);
    float* out = g_fsn + (size_t)gw * C_;
    out[lane]      = to_tf32(v0 * inv);   // tf32-matmul input semantics
    out[lane + 32] = to_tf32(v1 * inv);
    // ys is implicit: rows [0,1024) are fg (label 1), rest label 0
}

// -------- fused Gram (tf32 mma): only tiles with fg rows (it < 8) -----------
// grid (100, b=8), 256 thr = 8 warps (4 i-warps x 2 j-warps)
// labels constant per tile: pv = sum of jt<8 partials, dv = all 16.
__global__ void __launch_bounds__(256, 2) loss_mma_kernel() {
    extern __shared__ float smem[];
    float* xi = smem;            // 128 x 64
    float* xjs = smem + 8192;    // 128 x 64 (unused for diag tiles)
    __shared__ float rowd[128][2];
    __shared__ float cold[128][4];

    int b = blockIdx.y;
    int u = blockIdx.x;
    int it = 0;
    while (u >= NJT - it) { u -= NJT - it; ++it; }   // it in [0,8) for u<100
    int jt = it + u;
    bool diagT = (it == jt);
    bool needCol = (!diagT && jt < NFT);             // jt rows fg -> need col sums
    int t = threadIdx.x;

    const float4* src_i = (const float4*)(g_fsn + ((size_t)b * K_ + it * 128) * C_);
    const float4* src_j = (const float4*)(g_fsn + ((size_t)b * K_ + jt * 128) * C_);
    for (int q = t; q < 2048; q += 256) {
        int row = q >> 4, c4 = q & 15;
        int dst = (row << 6) + ((c4 ^ (row & 7)) << 2);
        *(float4*)(xi + dst) = src_i[q];
        if (!diagT) *(float4*)(xjs + dst) = src_j[q];   // diag: alias to xi
    }
    float* xj = diagT ? xi : xjs;
    __syncthreads();

    int w    = t >> 5;
    int lane = t & 31;
    int wi = w >> 1;             // 0..3 : i-strip of 32 rows
    int wj = w & 1;              // 0..1 : j-strip of 64 cols
    int g   = lane >> 2;         // groupID
    int tig = lane & 3;          // thread-in-group

    float c[2][8][4];
    #pragma unroll
    for (int m = 0; m < 2; ++m)
        #pragma unroll
        for (int n = 0; n < 8; ++n)
            { c[m][n][0]=0.f; c[m][n][1]=0.f; c[m][n][2]=0.f; c[m][n][3]=0.f; }

    #pragma unroll
    for (int ks = 0; ks < 8; ++ks) {
        int c4a = 2 * ks, c4b = 2 * ks + 1;
        float a[2][4];
        #pragma unroll
        for (int m = 0; m < 2; ++m) {
            int r0 = wi * 32 + m * 16 + g;
            int r1 = r0 + 8;
            int x0 = (r0 & 7);
            a[m][0] = xi[(r0 << 6) + ((c4a ^ x0) << 2) + tig];
            a[m][2] = xi[(r0 << 6) + ((c4b ^ x0) << 2) + tig];
            a[m][1] = xi[(r1 << 6) + ((c4a ^ x0) << 2) + tig];
            a[m][3] = xi[(r1 << 6) + ((c4b ^ x0) << 2) + tig];
        }
        float bf[8][2];
        #pragma unroll
        for (int n = 0; n < 8; ++n) {
            int jr = wj * 64 + n * 8 + g;
            int xo = (jr & 7);
            bf[n][0] = xj[(jr << 6) + ((c4a ^ xo) << 2) + tig];
            bf[n][1] = xj[(jr << 6) + ((c4b ^ xo) << 2) + tig];
        }
        #pragma unroll
        for (int m = 0; m < 2; ++m)
            #pragma unroll
            for (int n = 0; n < 8; ++n)
                mma_tf32(c[m][n], a[m], bf[n]);
    }

    // epilogue: exp + row sums (+ col sums when jt is fg), fixed order
    float cd0[8], cd1[8];
    #pragma unroll
    for (int n = 0; n < 8; ++n) { cd0[n] = 0.f; cd1[n] = 0.f; }

    #pragma unroll
    for (int m = 0; m < 2; ++m) {
        int r0 = wi * 32 + m * 16 + g;
        int r1 = r0 + 8;
        float d0 = 0.f, d1 = 0.f;
        #pragma unroll
        for (int n = 0; n < 8; ++n) {
            int col = wj * 64 + n * 8 + tig * 2;
            float e00 = ex2f(fmaf(c[m][n][0], C1_, C0_));
            float e01 = ex2f(fmaf(c[m][n][1], C1_, C0_));
            float e10 = ex2f(fmaf(c[m][n][2], C1_, C0_));
            float e11 = ex2f(fmaf(c[m][n][3], C1_, C0_));
            if (diagT) {
                if (r0 == col)     e00 = 0.f;
                if (r0 == col + 1) e01 = 0.f;
                if (r1 == col)     e10 = 0.f;
                if (r1 == col + 1) e11 = 0.f;
            }
            d0 += e00 + e01;
            d1 += e10 + e11;
            if (needCol) {
                cd0[n] += e00 + e10;
                cd1[n] += e01 + e11;
            }
        }
        #pragma unroll
        for (int o = 1; o <= 2; o <<= 1) {
            d0 += __shfl_xor_sync(0xFFFFFFFFu, d0, o);
            d1 += __shfl_xor_sync(0xFFFFFFFFu, d1, o);
        }
        if (tig == 0) {
            rowd[r0][wj] = d0;
            rowd[r1][wj] = d1;
        }
    }

    if (needCol) {
        #pragma unroll
        for (int n = 0; n < 8; ++n) {
            #pragma unroll
            for (int o = 4; o <= 16; o <<= 1) {
                cd0[n] += __shfl_xor_sync(0xFFFFFFFFu, cd0[n], o);
                cd1[n] += __shfl_xor_sync(0xFFFFFFFFu, cd1[n], o);
            }
        }
        if (lane < 4) {          // g == 0, tig == lane
            #pragma unroll
            for (int n = 0; n < 8; ++n) {
                int col = wj * 64 + n * 8 + lane * 2;
                cold[col][wi]     = cd0[n];
                cold[col + 1][wi] = cd1[n];
            }
        }
    }
    __syncthreads();
    if (t < 128) {
        int gi = b * K_ + it * 128 + t;
        g_d[gi * NJT + jt] = rowd[t][0] + rowd[t][1];
        if (needCol) {
            int gj = b * K_ + jt * 128 + t;
            g_d[gj * NJT + it] = ((cold[t][0] + cold[t][1]) + (cold[t][2] + cold[t][3]));
        }
    }
}

// -------- per-row loss (fg rows only) + per-image reduce --------
__global__ void __launch_bounds__(256) rowloss_kernel(float* out) {
    int b = blockIdx.x, t = threadIdx.x;
    float ls = 0.0f; int cnt = 0;
    for (int i = t; i < NFG; i += 256) {
        float pv = 0.0f;
        #pragma unroll
        for (int js = 0; js < NFT; ++js) pv += g_d[(b * K_ + i) * NJT + js];
        float dv = pv;
        #pragma unroll
        for (int js = NFT; js < NJT; ++js) dv += g_d[(b * K_ + i) * NJT + js];
        if (pv > 0.0f) {
            ls += logf(fmaxf(dv, 1e-8f)) - logf(fmaxf(pv, 1e-8f));
            cnt++;
        }
    }
    __shared__ float ss[256];
    __shared__ int   sc[256];
    ss[t] = ls; sc[t] = cnt;
    __syncthreads();
    for (int o = 128; o; o >>= 1) {
        if (t < o) { ss[t] += ss[t + o]; sc[t] += sc[t + o]; }
        __syncthreads();
    }
    if (t == 0) { g_loss_sum[b] = ss[0]; g_valid[b] = sc[0]; }
    __syncthreads();
    __shared__ int lastFlag;
    if (t == 0) {
        __threadfence();
        lastFlag = (atomicAdd(&g_rldone, 1u) == (unsigned)(B_ - 1));
    }
    __syncthreads();
    if (lastFlag && t == 0) {
        float s = 0.0f;
        for (int bb = 0; bb < B_; ++bb) {        // fixed order -> deterministic
            int v = g_valid[bb]; if (v < 1) v = 1;
            s += g_loss_sum[bb] / (float)v;
        }
        out[0] = s / (float)B_;
    }
}

// -------- launch --------
extern "C" void kernel_launch(void* const* d_in, const int* in_sizes, int n_in,
                              void* d_out, int out_size) {
    const float* feats  = (const float*)d_in[0];
    const int*   labels = (const int*)d_in[1];

    // Derive JAX keys host-side (deterministic; baked into graph as kernel args).
    KeyArg ka;
    uint32_t out16[16];
    for (int j = 0; j < 8; ++j)
        tf2x32(0u, 1u, (uint32_t)j, (uint32_t)(8 + j), out16[j], out16[8 + j]);
    for (int b = 0; b < B_; ++b) {
        uint32_t kb0 = out16[2 * b], kb1 = out16[2 * b + 1];
        uint32_t o6[6];
        for (int j = 0; j < 3; ++j)
            tf2x32(kb0, kb1, (uint32_t)j, (uint32_t)(3 + j), o6[j], o6[3 + j]);
        ka.k[b][0][0] = o6[0]; ka.k[b][0][1] = o6[1];   // k1 -> fg pick
        ka.k[b][1][0] = o6[2]; ka.k[b][1][1] = o6[3];   // k2 -> ring pick
        ka.k[b][2][0] = o6[4]; ka.k[b][2][1] = o6[5];   // k3 -> bg pick
    }

    // 64 KB dynamic smem opt-in (idempotent; one-shot; graph-safe)
    static_assert(2 * 128 * 64 * sizeof(float) == 65536, "smem size");
    static bool s_attr_done = false;
    if (!s_attr_done) {
        cudaFuncSetAttribute(loss_mma_kernel,
                             cudaFuncAttributeMaxDynamicSharedMemorySize, 65536);
        s_attr_done = true;
    }

    mask_kernel<<<dim3(8, B_), 256>>>(labels);
    select_kernel<<<dim3(NG, 32), 256>>>(ka);
    gather_kernel<<<(B_ * K_ * 32 + 255) / 256, 256>>>(feats);
    loss_mma_kernel<<<dim3(NTILES, B_), 256, 65536>>>();
    rowloss_kernel<<<B_, 256>>>((float*)d_out);
}